// round 4
// baseline (speedup 1.0000x reference)
#include <cuda_runtime.h>
#include <cstdint>
#include <cstddef>

// MultiHeadAttention fused kernel.
// GEMMs use 3xTF32 error-compensated mma.sync (hi/lo split): effective ~fp32
// precision on tensor cores. Attention (QK^T, softmax, PV) in fp32 CUDA cores.
// One CTA per batch element.

namespace {

constexpr int kT  = 32;    // sequence length
constexpr int kC  = 128;   // channels
constexpr int kHD = 32;    // head dim
constexpr int SPAD = 132;  // padded row stride (floats): (4r+c)%32 unique -> conflict-free frags
constexpr int WPAD = 36;   // padded row stride for per-warp softmax rows (16B-aligned)

// smem layout (floats). so_hi/so_lo alias sx_hi/sx_lo (x dead after phase 1).
constexpr int SM_XH  = 0;
constexpr int SM_XL  = SM_XH + kT * SPAD;
constexpr int SM_Q   = SM_XL + kT * SPAD;
constexpr int SM_K   = SM_Q  + kT * SPAD;
constexpr int SM_V   = SM_K  + kT * SPAD;
constexpr int SM_WEI = SM_V  + kT * SPAD;              // 8 warps * 16 rows * WPAD
constexpr int SMEM_FLOATS = SM_WEI + 8 * 16 * WPAD;
constexpr int SMEM_BYTES  = SMEM_FLOATS * 4;           // 102912 B -> 2 CTAs/SM

__device__ __forceinline__ float tf32r(float x) {
    uint32_t u;
    asm("cvt.rna.tf32.f32 %0, %1;" : "=r"(u) : "f"(x));
    return __uint_as_float(u);
}

__device__ __forceinline__ void mma_tf32(float d[4],
                                         uint32_t a0, uint32_t a1, uint32_t a2, uint32_t a3,
                                         uint32_t b0, uint32_t b1) {
    asm("mma.sync.aligned.m16n8k8.row.col.f32.tf32.tf32.f32 "
        "{%0,%1,%2,%3}, {%4,%5,%6,%7}, {%8,%9}, {%0,%1,%2,%3};"
        : "+f"(d[0]), "+f"(d[1]), "+f"(d[2]), "+f"(d[3])
        : "r"(a0), "r"(a1), "r"(a2), "r"(a3), "r"(b0), "r"(b1));
}

// C[32,128] += A[32,128] * W^T with 3xTF32 compensation.
// A given as hi/lo tf32 pair in smem (stride SPAD). W row-major [n=128][k=128]
// fp32 from global (L1-hot), hi/lo split on the fly.
// Warp w owns output cols [16w,16w+16) as two n8 tiles, both m16 tiles.
__device__ __forceinline__ void gemm3_acc(const float* __restrict__ sah,
                                          const float* __restrict__ sal,
                                          const float* __restrict__ W,
                                          int warp, int lane, float d[2][2][4]) {
    const int r  = lane >> 2;
    const int c  = lane & 3;
    const int n0 = warp * 16;
#pragma unroll
    for (int kk = 0; kk < 16; kk++) {
        const int k0 = kk * 8;
        uint32_t ah[2][4], al[2][4];
#pragma unroll
        for (int m = 0; m < 2; m++) {
            const int off = (m * 16 + r) * SPAD + k0 + c;
            ah[m][0] = __float_as_uint(sah[off]);
            ah[m][1] = __float_as_uint(sah[off + 8 * SPAD]);
            ah[m][2] = __float_as_uint(sah[off + 4]);
            ah[m][3] = __float_as_uint(sah[off + 8 * SPAD + 4]);
            al[m][0] = __float_as_uint(sal[off]);
            al[m][1] = __float_as_uint(sal[off + 8 * SPAD]);
            al[m][2] = __float_as_uint(sal[off + 4]);
            al[m][3] = __float_as_uint(sal[off + 8 * SPAD + 4]);
        }
#pragma unroll
        for (int nt = 0; nt < 2; nt++) {
            const int nrow = n0 + nt * 8 + r;
            const float w0 = W[nrow * kC + k0 + c];
            const float w1 = W[nrow * kC + k0 + 4 + c];
            const float w0h = tf32r(w0), w1h = tf32r(w1);
            const uint32_t b0h = __float_as_uint(w0h);
            const uint32_t b1h = __float_as_uint(w1h);
            const uint32_t b0l = __float_as_uint(tf32r(w0 - w0h));
            const uint32_t b1l = __float_as_uint(tf32r(w1 - w1h));
#pragma unroll
            for (int m = 0; m < 2; m++) {
                mma_tf32(d[m][nt], ah[m][0], ah[m][1], ah[m][2], ah[m][3], b0h, b1h);
                mma_tf32(d[m][nt], ah[m][0], ah[m][1], ah[m][2], ah[m][3], b0l, b1l);
                mma_tf32(d[m][nt], al[m][0], al[m][1], al[m][2], al[m][3], b0h, b1h);
            }
        }
    }
}

__device__ __forceinline__ void zero_acc(float d[2][2][4]) {
#pragma unroll
    for (int m = 0; m < 2; m++)
#pragma unroll
        for (int nt = 0; nt < 2; nt++)
#pragma unroll
            for (int i = 0; i < 4; i++) d[m][nt][i] = 0.f;
}

__device__ __forceinline__ void store_tile_smem(float* __restrict__ sdst,
                                                int warp, int lane,
                                                const float d[2][2][4]) {
    const int r  = lane >> 2;
    const int c2 = (lane & 3) * 2;
#pragma unroll
    for (int m = 0; m < 2; m++)
#pragma unroll
        for (int nt = 0; nt < 2; nt++) {
            const int row = m * 16 + r;
            const int col = warp * 16 + nt * 8 + c2;
            sdst[row * SPAD + col]           = d[m][nt][0];
            sdst[row * SPAD + col + 1]       = d[m][nt][1];
            sdst[(row + 8) * SPAD + col]     = d[m][nt][2];
            sdst[(row + 8) * SPAD + col + 1] = d[m][nt][3];
        }
}

__global__ __launch_bounds__(256, 2)
void mha_fused_kernel(const float* __restrict__ x,
                      const float* __restrict__ Wq,
                      const float* __restrict__ Wk,
                      const float* __restrict__ Wv,
                      const float* __restrict__ Wp,
                      const float* __restrict__ bp,
                      float* __restrict__ out) {
    extern __shared__ float smem[];
    float* sxh  = smem + SM_XH;
    float* sxl  = smem + SM_XL;
    float* sq   = smem + SM_Q;
    float* sk   = smem + SM_K;
    float* sv   = smem + SM_V;
    float* swei = smem + SM_WEI;
    float* soh  = sxh;   // alias: x dead after phase 1
    float* sol  = sxl;

    const int tid  = threadIdx.x;
    const int warp = tid >> 5;
    const int lane = tid & 31;
    const int b    = blockIdx.x;

    // ---- Phase 0: load x tile, split to tf32 hi/lo ----
    const float4* gx = reinterpret_cast<const float4*>(x + (size_t)b * kT * kC);
#pragma unroll
    for (int i = 0; i < 4; i++) {
        const int f  = tid + 256 * i;       // float4 index in [0,1024)
        const int t  = f >> 5;
        const int cc = f & 31;
        const float4 v = gx[f];
        float4 h, l;
        h.x = tf32r(v.x); l.x = tf32r(v.x - h.x);
        h.y = tf32r(v.y); l.y = tf32r(v.y - h.y);
        h.z = tf32r(v.z); l.z = tf32r(v.z - h.z);
        h.w = tf32r(v.w); l.w = tf32r(v.w - h.w);
        *reinterpret_cast<float4*>(sxh + t * SPAD + cc * 4) = h;
        *reinterpret_cast<float4*>(sxl + t * SPAD + cc * 4) = l;
    }
    __syncthreads();

    // ---- Phase 1: QKV projections (3xTF32) ----
    {
        float d[2][2][4];
        zero_acc(d);
        gemm3_acc(sxh, sxl, Wq, warp, lane, d);
        store_tile_smem(sq, warp, lane, d);

        zero_acc(d);
        gemm3_acc(sxh, sxl, Wk, warp, lane, d);
        store_tile_smem(sk, warp, lane, d);

        zero_acc(d);
        gemm3_acc(sxh, sxl, Wv, warp, lane, d);
        store_tile_smem(sv, warp, lane, d);
    }
    __syncthreads();

    // ---- Phase 2: causal attention per head (fp32) ----
    {
        const int h  = warp >> 1;
        const int t0 = (warp & 1) * 16;
        float* swp = swei + warp * 16 * WPAD;     // warp-private softmax rows
        const float NEG_INF = __int_as_float(0xff800000u);
        const float scale = 11.3137084989847604f; // sqrt(128); applied AFTER mask, like ref

        // lane s caches k[s, h*32 .. h*32+31]
        float kreg[32];
#pragma unroll
        for (int i = 0; i < 8; i++) {
            float4 kv = *reinterpret_cast<const float4*>(sk + lane * SPAD + h * kHD + 4 * i);
            kreg[4 * i + 0] = kv.x; kreg[4 * i + 1] = kv.y;
            kreg[4 * i + 2] = kv.z; kreg[4 * i + 3] = kv.w;
        }

#pragma unroll
        for (int tt = 0; tt < 16; tt++) {
            const int t = t0 + tt;
            const float4* qrow = reinterpret_cast<const float4*>(sq + t * SPAD + h * kHD);
            float acc = 0.f;
#pragma unroll
            for (int i = 0; i < 8; i++) {
                const float4 q4 = qrow[i];   // broadcast load
                acc = fmaf(q4.x, kreg[4 * i + 0], acc);
                acc = fmaf(q4.y, kreg[4 * i + 1], acc);
                acc = fmaf(q4.z, kreg[4 * i + 2], acc);
                acc = fmaf(q4.w, kreg[4 * i + 3], acc);
            }
            // mask to -inf first, then scale (matches reference; -inf*scale = -inf)
            float logit = (lane <= t) ? acc * scale : NEG_INF;
            float mx = logit;
#pragma unroll
            for (int off = 16; off; off >>= 1)
                mx = fmaxf(mx, __shfl_xor_sync(0xffffffffu, mx, off));
            const float p = __expf(logit - mx);   // exp(-inf) = 0 for masked lanes
            float s = p;
#pragma unroll
            for (int off = 16; off; off >>= 1)
                s += __shfl_xor_sync(0xffffffffu, s, off);
            swp[tt * WPAD + lane] = p * (1.0f / s);
        }
        __syncwarp();

        // lane d caches v[0..31, h*32 + d]
        float vreg[32];
#pragma unroll
        for (int ss = 0; ss < 32; ss++)
            vreg[ss] = sv[ss * SPAD + h * kHD + lane];

#pragma unroll
        for (int tt = 0; tt < 16; tt++) {
            const int t = t0 + tt;
            const float4* prow = reinterpret_cast<const float4*>(swp + tt * WPAD);
            float acc = 0.f;
#pragma unroll
            for (int i = 0; i < 8; i++) {
                const float4 p4 = prow[i];   // broadcast load
                acc = fmaf(p4.x, vreg[4 * i + 0], acc);
                acc = fmaf(p4.y, vreg[4 * i + 1], acc);
                acc = fmaf(p4.z, vreg[4 * i + 2], acc);
                acc = fmaf(p4.w, vreg[4 * i + 3], acc);
            }
            // hi/lo split for the output-projection mma A operand
            const float hi = tf32r(acc);
            soh[t * SPAD + h * kHD + lane] = hi;
            sol[t * SPAD + h * kHD + lane] = tf32r(acc - hi);
        }
    }
    __syncthreads();

    // ---- Phase 3: output projection (3xTF32) + bias, store to global ----
    {
        float d[2][2][4];
        zero_acc(d);
        gemm3_acc(soh, sol, Wp, warp, lane, d);

        const int r  = lane >> 2;
        const int c2 = (lane & 3) * 2;
        float* ob = out + (size_t)b * kT * kC;
#pragma unroll
        for (int m = 0; m < 2; m++)
#pragma unroll
            for (int nt = 0; nt < 2; nt++) {
                const int row = m * 16 + r;
                const int col = warp * 16 + nt * 8 + c2;
                const float b0v = bp[col];
                const float b1v = bp[col + 1];
                *reinterpret_cast<float2*>(ob + row * kC + col) =
                    make_float2(d[m][nt][0] + b0v, d[m][nt][1] + b1v);
                *reinterpret_cast<float2*>(ob + (row + 8) * kC + col) =
                    make_float2(d[m][nt][2] + b0v, d[m][nt][3] + b1v);
            }
    }
}

} // namespace

extern "C" void kernel_launch(void* const* d_in, const int* in_sizes, int n_in,
                              void* d_out, int out_size) {
    const float* x  = (const float*)d_in[0];
    const float* Wq = (const float*)d_in[1];
    const float* Wk = (const float*)d_in[2];
    const float* Wv = (const float*)d_in[3];
    const float* Wp = (const float*)d_in[4];
    const float* bp = (const float*)d_in[5];
    float* out = (float*)d_out;

    cudaFuncSetAttribute(mha_fused_kernel,
                         cudaFuncAttributeMaxDynamicSharedMemorySize, SMEM_BYTES);
    mha_fused_kernel<<<16384, 256, SMEM_BYTES>>>(x, Wq, Wk, Wv, Wp, bp, out);
}

// round 5
// speedup vs baseline: 1.2817x; 1.2817x over previous
#include <cuda_runtime.h>
#include <cstdint>
#include <cstddef>

// Fused MHA, round 4.
// 4 batch elements per CTA (512 threads, 16 warps). GEMMs: 3xTF32-compensated
// mma.sync with on-the-fly fp32->tf32 hi/lo split; W staged through smem in
// 16-column k-slices (double buffered). Attention: 1 warp per (batch, head).
// smem aliasing: sx holds x then o; sa holds q then p; sb holds k then v.

namespace {

constexpr int kT  = 32;
constexpr int kC  = 128;
constexpr int kHD = 32;
constexpr int kG  = 4;                 // batches per CTA
constexpr int ROWS = kG * kT;          // 128
constexpr int SPAD = 132;              // main tile stride (floats)
constexpr int WST  = 20;               // W stage stride (floats) for 16-col slice
constexpr int KB   = 16;               // k-slice width
constexpr int NKB  = kC / KB;          // 8

constexpr int SM_X = 0;
constexpr int SM_A = SM_X + ROWS * SPAD;        // q, then p
constexpr int SM_B = SM_A + ROWS * SPAD;        // k, then v
constexpr int SM_W = SM_B + ROWS * SPAD;        // W stage, 2 buffers
constexpr int SMEM_FLOATS = SM_W + 2 * kC * WST;
constexpr int SMEM_BYTES  = SMEM_FLOATS * 4;    // 223232 B -> 1 CTA/SM

__device__ __forceinline__ float tf32r(float x) {
    uint32_t u;
    asm("cvt.rna.tf32.f32 %0, %1;" : "=r"(u) : "f"(x));
    return __uint_as_float(u);
}

__device__ __forceinline__ void split2(float v, uint32_t& h, uint32_t& l) {
    const float hf = tf32r(v);
    h = __float_as_uint(hf);
    l = __float_as_uint(tf32r(v - hf));
}

__device__ __forceinline__ void mma_tf32(float d[4],
                                         uint32_t a0, uint32_t a1, uint32_t a2, uint32_t a3,
                                         uint32_t b0, uint32_t b1) {
    asm("mma.sync.aligned.m16n8k8.row.col.f32.tf32.tf32.f32 "
        "{%0,%1,%2,%3}, {%4,%5,%6,%7}, {%8,%9}, {%0,%1,%2,%3};"
        : "+f"(d[0]), "+f"(d[1]), "+f"(d[2]), "+f"(d[3])
        : "r"(a0), "r"(a1), "r"(a2), "r"(a3), "r"(b0), "r"(b1));
}

// C[128,128] = src[128,128](fp32 smem, stride SPAD) @ W^T, 3xTF32.
// Warp (mi,nj) of a 4x4 grid owns m-tiles {2mi,2mi+1} and n-cols [32nj,32nj+32).
// W staged through sw (2 x kC*WST floats) in KB-wide slices, 1 barrier/slice.
template<bool TOGLOBAL>
__device__ __forceinline__ void gemm3(const float* __restrict__ src,
                                      const float* __restrict__ Wg,
                                      float* __restrict__ dstS,
                                      float* __restrict__ dstG,
                                      const float* __restrict__ bias,
                                      float* __restrict__ sw,
                                      int tid) {
    const int warp = tid >> 5, lane = tid & 31;
    const int mi = warp >> 2, nj = warp & 3;
    const int r = lane >> 2, c = lane & 3;
    const int sn = tid >> 2;            // stage row 0..127
    const int sj = (tid & 3) * 4;       // stage col offset (float4)

    float d[2][4][4];
#pragma unroll
    for (int mt = 0; mt < 2; mt++)
#pragma unroll
        for (int nt = 0; nt < 4; nt++)
#pragma unroll
            for (int i = 0; i < 4; i++) d[mt][nt][i] = 0.f;

    // prologue: stage slice 0
    {
        float4 wv = *reinterpret_cast<const float4*>(Wg + sn * kC + sj);
        *reinterpret_cast<float4*>(sw + sn * WST + sj) = wv;
    }
    __syncthreads();

    for (int kb = 0; kb < NKB; kb++) {
        const float* swb = sw + (kb & 1) * (kC * WST);
        float4 wn;
        if (kb + 1 < NKB)
            wn = *reinterpret_cast<const float4*>(Wg + sn * kC + (kb + 1) * KB + sj);

#pragma unroll
        for (int ks = 0; ks < 2; ks++) {
            const int k0  = kb * KB + ks * 8;  // col in src
            const int k0l = ks * 8;            // col in stage
            uint32_t ah[2][4], al[2][4];
#pragma unroll
            for (int mt = 0; mt < 2; mt++) {
                const float* p = src + ((mi * 2 + mt) * 16 + r) * SPAD + k0 + c;
                split2(p[0],            ah[mt][0], al[mt][0]);
                split2(p[8 * SPAD],     ah[mt][1], al[mt][1]);
                split2(p[4],            ah[mt][2], al[mt][2]);
                split2(p[8 * SPAD + 4], ah[mt][3], al[mt][3]);
            }
#pragma unroll
            for (int nt = 0; nt < 4; nt++) {
                const int nrow = nj * 32 + nt * 8 + r;
                uint32_t b0h, b0l, b1h, b1l;
                split2(swb[nrow * WST + k0l + c],     b0h, b0l);
                split2(swb[nrow * WST + k0l + 4 + c], b1h, b1l);
#pragma unroll
                for (int mt = 0; mt < 2; mt++) {
                    mma_tf32(d[mt][nt], ah[mt][0], ah[mt][1], ah[mt][2], ah[mt][3], b0h, b1h);
                    mma_tf32(d[mt][nt], ah[mt][0], ah[mt][1], ah[mt][2], ah[mt][3], b0l, b1l);
                    mma_tf32(d[mt][nt], al[mt][0], al[mt][1], al[mt][2], al[mt][3], b0h, b1h);
                }
            }
        }
        if (kb + 1 < NKB)
            *reinterpret_cast<float4*>(sw + ((kb + 1) & 1) * (kC * WST) + sn * WST + sj) = wn;
        __syncthreads();
    }

    // epilogue
    const int c2 = (lane & 3) * 2;
#pragma unroll
    for (int mt = 0; mt < 2; mt++)
#pragma unroll
        for (int nt = 0; nt < 4; nt++) {
            const int row = (mi * 2 + mt) * 16 + r;
            const int col = nj * 32 + nt * 8 + c2;
            if (TOGLOBAL) {
                const float b0v = bias[col];
                const float b1v = bias[col + 1];
                *reinterpret_cast<float2*>(dstG + (size_t)row * kC + col) =
                    make_float2(d[mt][nt][0] + b0v, d[mt][nt][1] + b1v);
                *reinterpret_cast<float2*>(dstG + (size_t)(row + 8) * kC + col) =
                    make_float2(d[mt][nt][2] + b0v, d[mt][nt][3] + b1v);
            } else {
                *reinterpret_cast<float2*>(dstS + row * SPAD + col) =
                    make_float2(d[mt][nt][0], d[mt][nt][1]);
                *reinterpret_cast<float2*>(dstS + (row + 8) * SPAD + col) =
                    make_float2(d[mt][nt][2], d[mt][nt][3]);
            }
        }
}

__global__ __launch_bounds__(512, 1)
void mha_fused_kernel(const float* __restrict__ x,
                      const float* __restrict__ Wq,
                      const float* __restrict__ Wk,
                      const float* __restrict__ Wv,
                      const float* __restrict__ Wp,
                      const float* __restrict__ bp,
                      float* __restrict__ out) {
    extern __shared__ float smem[];
    float* sx = smem + SM_X;   // x, later o
    float* sa = smem + SM_A;   // q, later p
    float* sb = smem + SM_B;   // k, later v
    float* sw = smem + SM_W;

    const int tid  = threadIdx.x;
    const int warp = tid >> 5;
    const int lane = tid & 31;
    const int b0   = blockIdx.x * kG;

    // ---- load x for 4 batches (coalesced float4) ----
    const float4* gx = reinterpret_cast<const float4*>(x + (size_t)b0 * kT * kC);
#pragma unroll
    for (int i = 0; i < 8; i++) {
        const int f = tid + 512 * i;      // float4 index 0..4095
        const int row = f >> 5, col4 = f & 31;
        *reinterpret_cast<float4*>(sx + row * SPAD + col4 * 4) = gx[f];
    }
    __syncthreads();

    // ---- Q, K projections ----
    gemm3<false>(sx, Wq, sa, nullptr, nullptr, sw, tid);
    gemm3<false>(sx, Wk, sb, nullptr, nullptr, sw, tid);
    __syncthreads();

    // ---- attention: QK^T + softmax (warp-local, 1 warp per (batch, head)) ----
    {
        const int rb = (warp >> 2) * kT;
        const int cb = (warp & 3) * kHD;
        const float NEG_INF = __int_as_float(0xff800000u);
        const float scale = 11.3137084989847604f;  // sqrt(128), applied after mask

        float kreg[32];
#pragma unroll
        for (int i = 0; i < 8; i++) {
            const float4 kv = *reinterpret_cast<const float4*>(sb + (rb + lane) * SPAD + cb + 4 * i);
            kreg[4 * i + 0] = kv.x; kreg[4 * i + 1] = kv.y;
            kreg[4 * i + 2] = kv.z; kreg[4 * i + 3] = kv.w;
        }

#pragma unroll 8
        for (int t = 0; t < kT; t++) {
            const float4* qrow = reinterpret_cast<const float4*>(sa + (rb + t) * SPAD + cb);
            float acc = 0.f;
#pragma unroll
            for (int i = 0; i < 8; i++) {
                const float4 q4 = qrow[i];  // broadcast
                acc = fmaf(q4.x, kreg[4 * i + 0], acc);
                acc = fmaf(q4.y, kreg[4 * i + 1], acc);
                acc = fmaf(q4.z, kreg[4 * i + 2], acc);
                acc = fmaf(q4.w, kreg[4 * i + 3], acc);
            }
            float logit = (lane <= t) ? acc * scale : NEG_INF;
            float mx = logit;
#pragma unroll
            for (int off = 16; off; off >>= 1)
                mx = fmaxf(mx, __shfl_xor_sync(0xffffffffu, mx, off));
            const float e = __expf(logit - mx);
            float s = e;
#pragma unroll
            for (int off = 16; off; off >>= 1)
                s += __shfl_xor_sync(0xffffffffu, s, off);
            sa[(rb + t) * SPAD + cb + lane] = e * (1.0f / s);  // p overwrites q row t
        }
    }
    __syncthreads();

    // ---- V projection (overwrites k region) ----
    gemm3<false>(sx, Wv, sb, nullptr, nullptr, sw, tid);
    __syncthreads();

    // ---- PV: o = p @ v, written into sx (x dead) ----
    {
        const int rb = (warp >> 2) * kT;
        const int cb = (warp & 3) * kHD;
        float vreg[32];
#pragma unroll
        for (int s = 0; s < 32; s++)
            vreg[s] = sb[(rb + s) * SPAD + cb + lane];
#pragma unroll 8
        for (int t = 0; t < kT; t++) {
            const float4* prow = reinterpret_cast<const float4*>(sa + (rb + t) * SPAD + cb);
            float acc = 0.f;
#pragma unroll
            for (int i = 0; i < 8; i++) {
                const float4 p4 = prow[i];  // broadcast
                acc = fmaf(p4.x, vreg[4 * i + 0], acc);
                acc = fmaf(p4.y, vreg[4 * i + 1], acc);
                acc = fmaf(p4.z, vreg[4 * i + 2], acc);
                acc = fmaf(p4.w, vreg[4 * i + 3], acc);
            }
            sx[(rb + t) * SPAD + cb + lane] = acc;
        }
    }
    __syncthreads();

    // ---- output projection + bias -> global ----
    gemm3<true>(sx, Wp, nullptr, out + (size_t)b0 * kT * kC, bp, sw, tid);
}

} // namespace

extern "C" void kernel_launch(void* const* d_in, const int* in_sizes, int n_in,
                              void* d_out, int out_size) {
    const float* x  = (const float*)d_in[0];
    const float* Wq = (const float*)d_in[1];
    const float* Wk = (const float*)d_in[2];
    const float* Wv = (const float*)d_in[3];
    const float* Wp = (const float*)d_in[4];
    const float* bp = (const float*)d_in[5];
    float* out = (float*)d_out;

    cudaFuncSetAttribute(mha_fused_kernel,
                         cudaFuncAttributeMaxDynamicSharedMemorySize, SMEM_BYTES);
    mha_fused_kernel<<<16384 / kG, 512, SMEM_BYTES>>>(x, Wq, Wk, Wv, Wp, bp, out);
}

// round 6
// speedup vs baseline: 1.3248x; 1.0337x over previous
#include <cuda_runtime.h>
#include <cstdint>
#include <cstddef>

// Fused MHA, round 5.
// 4 batches/CTA, 512 threads. 3xTF32 mma.sync GEMMs with:
//  - weights pre-split (hi/lo tf32 planes) once by a prep kernel into device
//    globals -> zero cvt work on the B side in the hot loop
//  - A-side split via AND-mask + exact FADD (2 ALU ops/element, no cvt)
//  - W hi/lo planes staged in smem, double-buffered 8-col slices, stride 12
// Attention: 1 warp per (batch, head), fp32, warp-shuffle softmax.

namespace {

constexpr int kT  = 32;
constexpr int kC  = 128;
constexpr int kHD = 32;
constexpr int kG  = 4;                  // batches per CTA
constexpr int ROWS = kG * kT;           // 128
constexpr int SPAD = 132;               // tile stride: (4r+c)%32 distinct -> conflict-free
constexpr int KB   = 8;                 // k-slice width
constexpr int NKB  = kC / KB;           // 16
constexpr int WST  = 12;                // stage stride: (12r+c)%32 distinct -> conflict-free

// pre-split weights: [matrix q,k,v,p][hi|lo][128*128]
__device__ float g_wsp[4][2][kC * kC];

constexpr int SM_X = 0;
constexpr int SM_A = SM_X + ROWS * SPAD;           // q, then p
constexpr int SM_B = SM_A + ROWS * SPAD;           // k, then v
constexpr int SM_W = SM_B + ROWS * SPAD;           // 2 buffers x (hi plane + lo plane)
constexpr int WBUF = 2 * kC * WST;                 // one buffer = hi+lo planes
constexpr int SMEM_FLOATS = SM_W + 2 * WBUF;
constexpr int SMEM_BYTES  = SMEM_FLOATS * 4;       // 227328 B -> 1 CTA/SM

__device__ __forceinline__ float tf32r(float x) {
    uint32_t u;
    asm("cvt.rna.tf32.f32 %0, %1;" : "=r"(u) : "f"(x));
    return __uint_as_float(u);
}

// A-side cheap split: hi = truncate-to-tf32 (mask), lo = exact residual.
__device__ __forceinline__ void splitA(float v, uint32_t& h, uint32_t& l) {
    const uint32_t hb = __float_as_uint(v) & 0xffffe000u;   // LOP3
    h = hb;
    l = __float_as_uint(v - __uint_as_float(hb));           // FADD, exact; HW truncates at mma
}

__device__ __forceinline__ void mma_tf32(float d[4],
                                         uint32_t a0, uint32_t a1, uint32_t a2, uint32_t a3,
                                         uint32_t b0, uint32_t b1) {
    asm("mma.sync.aligned.m16n8k8.row.col.f32.tf32.tf32.f32 "
        "{%0,%1,%2,%3}, {%4,%5,%6,%7}, {%8,%9}, {%0,%1,%2,%3};"
        : "+f"(d[0]), "+f"(d[1]), "+f"(d[2]), "+f"(d[3])
        : "r"(a0), "r"(a1), "r"(a2), "r"(a3), "r"(b0), "r"(b1));
}

// C[128,128] = src[128,128](fp32 smem, stride SPAD) @ W^T, 3xTF32.
// Warp (mi,nj) in a 4x4 grid: m-tiles {2mi,2mi+1}, n-cols [32nj,32nj+32).
// W hi/lo planes staged through smem, double buffered, one 8-col slice per step.
template<bool TOGLOBAL>
__device__ __forceinline__ void gemm3(const float* __restrict__ src,
                                      int widx,
                                      float* __restrict__ dstS,
                                      float* __restrict__ dstG,
                                      const float* __restrict__ bias,
                                      float* __restrict__ sw,
                                      int tid) {
    const int warp = tid >> 5, lane = tid & 31;
    const int mi = warp >> 2, nj = warp & 3;
    const int r = lane >> 2, c = lane & 3;
    // staging role: threads 0..255 -> hi plane, 256..511 -> lo plane
    const int plane = tid >> 8;
    const int srow  = (tid & 255) >> 1;           // 0..127
    const int scol  = (tid & 1) * 4;              // 0 or 4
    const float* __restrict__ G = g_wsp[widx][plane];
    float* const stage_thr = sw + plane * (kC * WST) + srow * WST + scol;

    float d[2][4][4];
#pragma unroll
    for (int mt = 0; mt < 2; mt++)
#pragma unroll
        for (int nt = 0; nt < 4; nt++)
#pragma unroll
            for (int i = 0; i < 4; i++) d[mt][nt][i] = 0.f;

    // prologue: stage slice 0 into buffer 0
    float4 w = *reinterpret_cast<const float4*>(G + srow * kC + scol);
    *reinterpret_cast<float4*>(stage_thr) = w;
    __syncthreads();

#pragma unroll 2
    for (int kb = 0; kb < NKB; kb++) {
        const float* swb = sw + (kb & 1) * WBUF;
        const float* swh = swb;                    // hi plane
        const float* swl = swb + kC * WST;         // lo plane

        // prefetch next slice (latency hidden behind compute)
        if (kb + 1 < NKB)
            w = *reinterpret_cast<const float4*>(G + srow * kC + (kb + 1) * KB + scol);

        const int k0 = kb * KB;
        uint32_t ah[2][4], al[2][4];
#pragma unroll
        for (int mt = 0; mt < 2; mt++) {
            const float* p = src + ((mi * 2 + mt) * 16 + r) * SPAD + k0 + c;
            splitA(p[0],            ah[mt][0], al[mt][0]);
            splitA(p[8 * SPAD],     ah[mt][1], al[mt][1]);
            splitA(p[4],            ah[mt][2], al[mt][2]);
            splitA(p[8 * SPAD + 4], ah[mt][3], al[mt][3]);
        }
#pragma unroll
        for (int nt = 0; nt < 4; nt++) {
            const int nrow = nj * 32 + nt * 8 + r;
            const uint32_t b0h = __float_as_uint(swh[nrow * WST + c]);
            const uint32_t b1h = __float_as_uint(swh[nrow * WST + 4 + c]);
            const uint32_t b0l = __float_as_uint(swl[nrow * WST + c]);
            const uint32_t b1l = __float_as_uint(swl[nrow * WST + 4 + c]);
#pragma unroll
            for (int mt = 0; mt < 2; mt++) {
                mma_tf32(d[mt][nt], ah[mt][0], ah[mt][1], ah[mt][2], ah[mt][3], b0h, b1h);
                mma_tf32(d[mt][nt], ah[mt][0], ah[mt][1], ah[mt][2], ah[mt][3], b0l, b1l);
                mma_tf32(d[mt][nt], al[mt][0], al[mt][1], al[mt][2], al[mt][3], b0h, b1h);
            }
        }

        // write next slice into the other buffer, then one barrier per step
        if (kb + 1 < NKB)
            *reinterpret_cast<float4*>(sw + ((kb + 1) & 1) * WBUF +
                                       plane * (kC * WST) + srow * WST + scol) = w;
        __syncthreads();
    }

    // epilogue
    const int c2 = (lane & 3) * 2;
#pragma unroll
    for (int mt = 0; mt < 2; mt++)
#pragma unroll
        for (int nt = 0; nt < 4; nt++) {
            const int row = (mi * 2 + mt) * 16 + r;
            const int col = nj * 32 + nt * 8 + c2;
            if (TOGLOBAL) {
                const float b0v = bias[col];
                const float b1v = bias[col + 1];
                *reinterpret_cast<float2*>(dstG + (size_t)row * kC + col) =
                    make_float2(d[mt][nt][0] + b0v, d[mt][nt][1] + b1v);
                *reinterpret_cast<float2*>(dstG + (size_t)(row + 8) * kC + col) =
                    make_float2(d[mt][nt][2] + b0v, d[mt][nt][3] + b1v);
            } else {
                *reinterpret_cast<float2*>(dstS + row * SPAD + col) =
                    make_float2(d[mt][nt][0], d[mt][nt][1]);
                *reinterpret_cast<float2*>(dstS + (row + 8) * SPAD + col) =
                    make_float2(d[mt][nt][2], d[mt][nt][3]);
            }
        }
}

__global__ void presplit_kernel(const float* __restrict__ Wq,
                                const float* __restrict__ Wk,
                                const float* __restrict__ Wv,
                                const float* __restrict__ Wp) {
    const float* src[4] = {Wq, Wk, Wv, Wp};
    const int i = blockIdx.x * blockDim.x + threadIdx.x;   // 0..16383
#pragma unroll
    for (int m = 0; m < 4; m++) {
        const float v  = src[m][i];
        const float hi = tf32r(v);
        g_wsp[m][0][i] = hi;
        g_wsp[m][1][i] = tf32r(v - hi);
    }
}

__global__ __launch_bounds__(512, 1)
void mha_fused_kernel(const float* __restrict__ x,
                      const float* __restrict__ bp,
                      float* __restrict__ out) {
    extern __shared__ float smem[];
    float* sx = smem + SM_X;   // x, later o
    float* sa = smem + SM_A;   // q, later p
    float* sb = smem + SM_B;   // k, later v
    float* sw = smem + SM_W;

    const int tid  = threadIdx.x;
    const int warp = tid >> 5;
    const int lane = tid & 31;
    const int b0   = blockIdx.x * kG;

    // ---- load x for 4 batches ----
    const float4* gx = reinterpret_cast<const float4*>(x + (size_t)b0 * kT * kC);
#pragma unroll
    for (int i = 0; i < 8; i++) {
        const int f = tid + 512 * i;
        const int row = f >> 5, col4 = f & 31;
        *reinterpret_cast<float4*>(sx + row * SPAD + col4 * 4) = gx[f];
    }
    __syncthreads();

    // ---- Q, K projections ----
    gemm3<false>(sx, 0, sa, nullptr, nullptr, sw, tid);
    gemm3<false>(sx, 1, sb, nullptr, nullptr, sw, tid);
    __syncthreads();

    // ---- QK^T + causal softmax (1 warp per (batch, head)) ----
    {
        const int rb = (warp >> 2) * kT;
        const int cb = (warp & 3) * kHD;
        const float NEG_INF = __int_as_float(0xff800000u);
        const float scale = 11.3137084989847604f;  // sqrt(128), applied after mask

        float kreg[32];
#pragma unroll
        for (int i = 0; i < 8; i++) {
            const float4 kv = *reinterpret_cast<const float4*>(sb + (rb + lane) * SPAD + cb + 4 * i);
            kreg[4 * i + 0] = kv.x; kreg[4 * i + 1] = kv.y;
            kreg[4 * i + 2] = kv.z; kreg[4 * i + 3] = kv.w;
        }
#pragma unroll 8
        for (int t = 0; t < kT; t++) {
            const float4* qrow = reinterpret_cast<const float4*>(sa + (rb + t) * SPAD + cb);
            float acc = 0.f;
#pragma unroll
            for (int i = 0; i < 8; i++) {
                const float4 q4 = qrow[i];  // broadcast
                acc = fmaf(q4.x, kreg[4 * i + 0], acc);
                acc = fmaf(q4.y, kreg[4 * i + 1], acc);
                acc = fmaf(q4.z, kreg[4 * i + 2], acc);
                acc = fmaf(q4.w, kreg[4 * i + 3], acc);
            }
            float logit = (lane <= t) ? acc * scale : NEG_INF;
            float mx = logit;
#pragma unroll
            for (int off = 16; off; off >>= 1)
                mx = fmaxf(mx, __shfl_xor_sync(0xffffffffu, mx, off));
            const float e = __expf(logit - mx);
            float s = e;
#pragma unroll
            for (int off = 16; off; off >>= 1)
                s += __shfl_xor_sync(0xffffffffu, s, off);
            sa[(rb + t) * SPAD + cb + lane] = e * (1.0f / s);  // p overwrites q
        }
    }
    __syncthreads();

    // ---- V projection (overwrites k) ----
    gemm3<false>(sx, 2, sb, nullptr, nullptr, sw, tid);
    __syncthreads();

    // ---- PV: o = p @ v -> sx (x dead) ----
    {
        const int rb = (warp >> 2) * kT;
        const int cb = (warp & 3) * kHD;
        float vreg[32];
#pragma unroll
        for (int s = 0; s < 32; s++)
            vreg[s] = sb[(rb + s) * SPAD + cb + lane];
#pragma unroll 8
        for (int t = 0; t < kT; t++) {
            const float4* prow = reinterpret_cast<const float4*>(sa + (rb + t) * SPAD + cb);
            float acc = 0.f;
#pragma unroll
            for (int i = 0; i < 8; i++) {
                const float4 p4 = prow[i];  // broadcast
                acc = fmaf(p4.x, vreg[4 * i + 0], acc);
                acc = fmaf(p4.y, vreg[4 * i + 1], acc);
                acc = fmaf(p4.z, vreg[4 * i + 2], acc);
                acc = fmaf(p4.w, vreg[4 * i + 3], acc);
            }
            sx[(rb + t) * SPAD + cb + lane] = acc;
        }
    }
    __syncthreads();

    // ---- output projection + bias -> global ----
    gemm3<true>(sx, 3, nullptr, out + (size_t)b0 * kT * kC, bp, sw, tid);
}

} // namespace

extern "C" void kernel_launch(void* const* d_in, const int* in_sizes, int n_in,
                              void* d_out, int out_size) {
    const float* x  = (const float*)d_in[0];
    const float* Wq = (const float*)d_in[1];
    const float* Wk = (const float*)d_in[2];
    const float* Wv = (const float*)d_in[3];
    const float* Wp = (const float*)d_in[4];
    const float* bp = (const float*)d_in[5];
    float* out = (float*)d_out;

    presplit_kernel<<<64, 256>>>(Wq, Wk, Wv, Wp);

    cudaFuncSetAttribute(mha_fused_kernel,
                         cudaFuncAttributeMaxDynamicSharedMemorySize, SMEM_BYTES);
    mha_fused_kernel<<<16384 / kG, 512, SMEM_BYTES>>>(x, bp, out);
}

// round 7
// speedup vs baseline: 1.4615x; 1.1031x over previous
#include <cuda_runtime.h>
#include <cstdint>
#include <cstddef>

// Fused MHA, round 6.
// 2 batches/CTA, 256 threads (8 warps), 2 CTAs/SM. 3xTF32 mma.sync GEMMs.
//  - Weights pre-split + pre-swizzled into g_wsp2[mat][kb][nrow][quad]:
//    each lane's (b0h,b1h,b0l,b1l) is one aligned LDG.128 straight from L2.
//  - No smem weight staging, no intra-gemm barriers; 1-slice register prefetch.
//  - Warp owns 16 n-cols x all 64 rows -> zero cross-warp B redundancy.
// Attention: 1 warp per (batch, head), fp32, warp-shuffle softmax.

namespace {

constexpr int kT  = 32;
constexpr int kC  = 128;
constexpr int kHD = 32;
constexpr int kG  = 2;                  // batches per CTA
constexpr int ROWS = kG * kT;           // 64
constexpr int SPAD = 132;               // tile stride: (4r+c)%32 distinct -> conflict-free
constexpr int NKB  = 16;                // k-slices of width 8

// pre-split, pre-swizzled weights: [mat][kb][nrow][c-quad: b0h,b1h,b0l,b1l]
__device__ float g_wsp2[4][NKB][kC][16];

constexpr int SM_X = 0;
constexpr int SM_A = SM_X + ROWS * SPAD;   // q, then p
constexpr int SM_B = SM_A + ROWS * SPAD;   // k, then v
constexpr int SMEM_FLOATS = SM_B + ROWS * SPAD;
constexpr int SMEM_BYTES  = SMEM_FLOATS * 4;   // 101376 B -> 2 CTAs/SM

__device__ __forceinline__ float tf32r(float x) {
    uint32_t u;
    asm("cvt.rna.tf32.f32 %0, %1;" : "=r"(u) : "f"(x));
    return __uint_as_float(u);
}

// A-side cheap split: hi = truncate-to-tf32 (mask), lo = exact residual.
__device__ __forceinline__ void splitA(float v, uint32_t& h, uint32_t& l) {
    const uint32_t hb = __float_as_uint(v) & 0xffffe000u;   // LOP3
    h = hb;
    l = __float_as_uint(v - __uint_as_float(hb));           // exact FADD; HW truncates at mma
}

__device__ __forceinline__ void mma_tf32(float d[4],
                                         uint32_t a0, uint32_t a1, uint32_t a2, uint32_t a3,
                                         uint32_t b0, uint32_t b1) {
    asm("mma.sync.aligned.m16n8k8.row.col.f32.tf32.tf32.f32 "
        "{%0,%1,%2,%3}, {%4,%5,%6,%7}, {%8,%9}, {%0,%1,%2,%3};"
        : "+f"(d[0]), "+f"(d[1]), "+f"(d[2]), "+f"(d[3])
        : "r"(a0), "r"(a1), "r"(a2), "r"(a3), "r"(b0), "r"(b1));
}

// C[64,128] = src[64,128](fp32 smem, stride SPAD) @ W^T, 3xTF32, barrier-free.
// Warp nj (0..7) owns n-cols [16nj, 16nj+16) (2 n8 tiles) x all 4 m16 tiles.
template<bool TOGLOBAL>
__device__ __forceinline__ void gemm3(const float* __restrict__ src,
                                      int widx,
                                      float* __restrict__ dstS,
                                      float* __restrict__ dstG,
                                      const float* __restrict__ bias,
                                      int tid) {
    const int warp = tid >> 5, lane = tid & 31;
    const int r = lane >> 2, c = lane & 3;
    const float4* __restrict__ B = reinterpret_cast<const float4*>(&g_wsp2[widx][0][0][0]);
    // quad index for (kb, nt): (kb*128 + warp*16 + nt*8 + r)*4 + c
    const int bbase = (warp * 16 + r) * 4 + c;

    float d[4][2][4];
#pragma unroll
    for (int mt = 0; mt < 4; mt++)
#pragma unroll
        for (int nt = 0; nt < 2; nt++)
#pragma unroll
            for (int i = 0; i < 4; i++) d[mt][nt][i] = 0.f;

    float4 bc[2], bn[2];
    bc[0] = B[bbase];
    bc[1] = B[bbase + 32];

#pragma unroll
    for (int kb = 0; kb < NKB; kb++) {
        if (kb + 1 < NKB) {
            bn[0] = B[(kb + 1) * 512 + bbase];
            bn[1] = B[(kb + 1) * 512 + bbase + 32];
        }
        // A fragments for 4 m-tiles (hi/lo split on the fly)
        uint32_t ah[4][4], al[4][4];
#pragma unroll
        for (int mt = 0; mt < 4; mt++) {
            const float* p = src + (mt * 16 + r) * SPAD + kb * 8 + c;
            splitA(p[0],            ah[mt][0], al[mt][0]);
            splitA(p[8 * SPAD],     ah[mt][1], al[mt][1]);
            splitA(p[4],            ah[mt][2], al[mt][2]);
            splitA(p[8 * SPAD + 4], ah[mt][3], al[mt][3]);
        }
#pragma unroll
        for (int nt = 0; nt < 2; nt++) {
            const uint32_t b0h = __float_as_uint(bc[nt].x);
            const uint32_t b1h = __float_as_uint(bc[nt].y);
            const uint32_t b0l = __float_as_uint(bc[nt].z);
            const uint32_t b1l = __float_as_uint(bc[nt].w);
#pragma unroll
            for (int mt = 0; mt < 4; mt++) {
                mma_tf32(d[mt][nt], ah[mt][0], ah[mt][1], ah[mt][2], ah[mt][3], b0h, b1h);
                mma_tf32(d[mt][nt], ah[mt][0], ah[mt][1], ah[mt][2], ah[mt][3], b0l, b1l);
                mma_tf32(d[mt][nt], al[mt][0], al[mt][1], al[mt][2], al[mt][3], b0h, b1h);
            }
        }
        bc[0] = bn[0];
        bc[1] = bn[1];
    }

    // epilogue
    const int c2 = (lane & 3) * 2;
#pragma unroll
    for (int mt = 0; mt < 4; mt++)
#pragma unroll
        for (int nt = 0; nt < 2; nt++) {
            const int row = mt * 16 + r;
            const int col = warp * 16 + nt * 8 + c2;
            if (TOGLOBAL) {
                const float b0v = bias[col];
                const float b1v = bias[col + 1];
                *reinterpret_cast<float2*>(dstG + (size_t)row * kC + col) =
                    make_float2(d[mt][nt][0] + b0v, d[mt][nt][1] + b1v);
                *reinterpret_cast<float2*>(dstG + (size_t)(row + 8) * kC + col) =
                    make_float2(d[mt][nt][2] + b0v, d[mt][nt][3] + b1v);
            } else {
                *reinterpret_cast<float2*>(dstS + row * SPAD + col) =
                    make_float2(d[mt][nt][0], d[mt][nt][1]);
                *reinterpret_cast<float2*>(dstS + (row + 8) * SPAD + col) =
                    make_float2(d[mt][nt][2], d[mt][nt][3]);
            }
        }
}

// Pre-split + swizzle: one thread per (mat, kb, nrow, c) writes one float4 quad.
__global__ void presplit_kernel(const float* __restrict__ Wq,
                                const float* __restrict__ Wk,
                                const float* __restrict__ Wv,
                                const float* __restrict__ Wp) {
    const float* src[4] = {Wq, Wk, Wv, Wp};
    const int idx = blockIdx.x * blockDim.x + threadIdx.x;   // 0..32767
    const int c    = idx & 3;
    const int nrow = (idx >> 2) & 127;
    const int kb   = (idx >> 9) & 15;
    const int m    = idx >> 13;
    const float w0 = src[m][nrow * kC + kb * 8 + c];
    const float w1 = src[m][nrow * kC + kb * 8 + 4 + c];
    const float h0 = tf32r(w0), h1 = tf32r(w1);
    float4 q;
    q.x = h0;
    q.y = h1;
    q.z = tf32r(w0 - h0);
    q.w = tf32r(w1 - h1);
    *reinterpret_cast<float4*>(&g_wsp2[m][kb][nrow][c * 4]) = q;
}

__global__ __launch_bounds__(256, 2)
void mha_fused_kernel(const float* __restrict__ x,
                      const float* __restrict__ bp,
                      float* __restrict__ out) {
    extern __shared__ float smem[];
    float* sx = smem + SM_X;   // x, later o
    float* sa = smem + SM_A;   // q, later p
    float* sb = smem + SM_B;   // k, later v

    const int tid  = threadIdx.x;
    const int warp = tid >> 5;
    const int lane = tid & 31;
    const int b0   = blockIdx.x * kG;

    // ---- load x for 2 batches (coalesced float4) ----
    const float4* gx = reinterpret_cast<const float4*>(x + (size_t)b0 * kT * kC);
#pragma unroll
    for (int i = 0; i < 8; i++) {
        const int f = tid + 256 * i;      // 0..2047
        const int row = f >> 5, col4 = f & 31;
        *reinterpret_cast<float4*>(sx + row * SPAD + col4 * 4) = gx[f];
    }
    __syncthreads();

    // ---- Q, K projections (barrier-free internally) ----
    gemm3<false>(sx, 0, sa, nullptr, nullptr, tid);
    gemm3<false>(sx, 1, sb, nullptr, nullptr, tid);
    __syncthreads();

    // ---- QK^T + causal softmax: warp = (batch, head) ----
    {
        const int rb = (warp >> 2) * kT;       // batch block
        const int cb = (warp & 3) * kHD;       // head cols
        const float NEG_INF = __int_as_float(0xff800000u);
        const float scale = 11.3137084989847604f;  // sqrt(128), applied after mask

        float kreg[32];
#pragma unroll
        for (int i = 0; i < 8; i++) {
            const float4 kv = *reinterpret_cast<const float4*>(sb + (rb + lane) * SPAD + cb + 4 * i);
            kreg[4 * i + 0] = kv.x; kreg[4 * i + 1] = kv.y;
            kreg[4 * i + 2] = kv.z; kreg[4 * i + 3] = kv.w;
        }
#pragma unroll 8
        for (int t = 0; t < kT; t++) {
            const float4* qrow = reinterpret_cast<const float4*>(sa + (rb + t) * SPAD + cb);
            float acc = 0.f;
#pragma unroll
            for (int i = 0; i < 8; i++) {
                const float4 q4 = qrow[i];  // broadcast
                acc = fmaf(q4.x, kreg[4 * i + 0], acc);
                acc = fmaf(q4.y, kreg[4 * i + 1], acc);
                acc = fmaf(q4.z, kreg[4 * i + 2], acc);
                acc = fmaf(q4.w, kreg[4 * i + 3], acc);
            }
            float logit = (lane <= t) ? acc * scale : NEG_INF;
            float mx = logit;
#pragma unroll
            for (int off = 16; off; off >>= 1)
                mx = fmaxf(mx, __shfl_xor_sync(0xffffffffu, mx, off));
            const float e = __expf(logit - mx);
            float s = e;
#pragma unroll
            for (int off = 16; off; off >>= 1)
                s += __shfl_xor_sync(0xffffffffu, s, off);
            sa[(rb + t) * SPAD + cb + lane] = e * (1.0f / s);  // p overwrites q
        }
    }
    __syncthreads();

    // ---- V projection (overwrites k) ----
    gemm3<false>(sx, 2, sb, nullptr, nullptr, tid);
    __syncthreads();

    // ---- PV: o = p @ v -> sx (x dead) ----
    {
        const int rb = (warp >> 2) * kT;
        const int cb = (warp & 3) * kHD;
        float vreg[32];
#pragma unroll
        for (int s = 0; s < 32; s++)
            vreg[s] = sb[(rb + s) * SPAD + cb + lane];
#pragma unroll 8
        for (int t = 0; t < kT; t++) {
            const float4* prow = reinterpret_cast<const float4*>(sa + (rb + t) * SPAD + cb);
            float acc = 0.f;
#pragma unroll
            for (int i = 0; i < 8; i++) {
                const float4 p4 = prow[i];  // broadcast
                acc = fmaf(p4.x, vreg[4 * i + 0], acc);
                acc = fmaf(p4.y, vreg[4 * i + 1], acc);
                acc = fmaf(p4.z, vreg[4 * i + 2], acc);
                acc = fmaf(p4.w, vreg[4 * i + 3], acc);
            }
            sx[(rb + t) * SPAD + cb + lane] = acc;
        }
    }
    __syncthreads();

    // ---- output projection + bias -> global ----
    gemm3<true>(sx, 3, nullptr, out + (size_t)b0 * kT * kC, bp, tid);
}

} // namespace

extern "C" void kernel_launch(void* const* d_in, const int* in_sizes, int n_in,
                              void* d_out, int out_size) {
    const float* x  = (const float*)d_in[0];
    const float* Wq = (const float*)d_in[1];
    const float* Wk = (const float*)d_in[2];
    const float* Wv = (const float*)d_in[3];
    const float* Wp = (const float*)d_in[4];
    const float* bp = (const float*)d_in[5];
    float* out = (float*)d_out;

    presplit_kernel<<<128, 256>>>(Wq, Wk, Wv, Wp);

    cudaFuncSetAttribute(mha_fused_kernel,
                         cudaFuncAttributeMaxDynamicSharedMemorySize, SMEM_BYTES);
    mha_fused_kernel<<<16384 / kG, 256, SMEM_BYTES>>>(x, bp, out);
}

// round 10
// speedup vs baseline: 2.0389x; 1.3951x over previous
#include <cuda_runtime.h>
#include <cuda_bf16.h>
#include <cstdint>
#include <cstddef>

// Fused MHA, round 7.
// 2 batches/CTA, 256 threads, 2 CTAs/SM. GEMMs: 3-term bf16x2 compensated
// mma.sync.m16n8k16 (Ah*Bh + Ah*Bl + Al*Bh), effective ~17 mantissa bits.
//  - x split ONCE at load into packed bf16x2 hi/lo smem planes; o written
//    directly as hi/lo planes by the PV epilogue -> zero split work in gemms.
//  - Weights pre-split/pre-swizzled: one LDG.128 = full B frag (bh0,bh1,bl0,bl1).
//  - Attention fp32 with 4-way split accumulator chains.

namespace {

constexpr int kT  = 32;
constexpr int kC  = 128;
constexpr int kHD = 32;
constexpr int kG  = 2;                  // batches per CTA
constexpr int ROWS = kG * kT;           // 64
constexpr int SPAD = 132;               // fp32 tile stride (floats)
constexpr int APAD = 68;                // packed-pair plane stride (b32 units): (4g+c)%32 distinct
constexpr int NKB  = 8;                 // k-slices of width 16

// pre-split weights: [mat][kb][n8 tile][lane] = (bh0,bh1,bl0,bl1)
__device__ uint4 g_wb[4 * NKB * 16 * 32];   // 256 KB

// smem words (4B): xh, xl (later oh, ol), sa (q->p), sb (k->v)
constexpr int SM_XH = 0;
constexpr int SM_XL = SM_XH + ROWS * APAD;
constexpr int SM_A  = SM_XL + ROWS * APAD;
constexpr int SM_B  = SM_A + ROWS * SPAD;
constexpr int SMEM_WORDS = SM_B + ROWS * SPAD;
constexpr int SMEM_BYTES = SMEM_WORDS * 4;   // 102400 B -> 2 CTAs/SM

__device__ __forceinline__ uint32_t packbf(float hi_el, float lo_el) {
    uint32_t r;
    asm("cvt.rn.bf16x2.f32 %0, %1, %2;" : "=r"(r) : "f"(hi_el), "f"(lo_el));
    return r;
}

// split fp32 pair (x0 -> low, x1 -> high) into packed bf16 hi + residual-lo words
__device__ __forceinline__ void split_pair(float x0, float x1, uint32_t& h2, uint32_t& l2) {
    h2 = packbf(x1, x0);
    const float h0 = __bfloat162float(__ushort_as_bfloat16((unsigned short)(h2 & 0xffffu)));
    const float h1 = __bfloat162float(__ushort_as_bfloat16((unsigned short)(h2 >> 16)));
    l2 = packbf(x1 - h1, x0 - h0);   // residuals exact in fp32
}

__device__ __forceinline__ void mma_bf16(float d[4],
                                         uint32_t a0, uint32_t a1, uint32_t a2, uint32_t a3,
                                         uint32_t b0, uint32_t b1) {
    asm("mma.sync.aligned.m16n8k16.row.col.f32.bf16.bf16.f32 "
        "{%0,%1,%2,%3}, {%4,%5,%6,%7}, {%8,%9}, {%0,%1,%2,%3};"
        : "+f"(d[0]), "+f"(d[1]), "+f"(d[2]), "+f"(d[3])
        : "r"(a0), "r"(a1), "r"(a2), "r"(a3), "r"(b0), "r"(b1));
}

// C[64,128] = A[64,128] @ W^T, 3-term bf16x2, barrier-free.
// A: packed bf16x2 hi/lo planes in smem (stride APAD b32 col-pairs).
// Warp nj owns n-cols [16nj,16nj+16) (2 n8 tiles) x 4 m16 tiles.
template<bool TOGLOBAL>
__device__ __forceinline__ void gemm3bf(const uint32_t* __restrict__ srcH,
                                        const uint32_t* __restrict__ srcL,
                                        int widx,
                                        float* __restrict__ dstS,
                                        float* __restrict__ dstG,
                                        const float* __restrict__ bias,
                                        int tid) {
    const int warp = tid >> 5, lane = tid & 31;
    const int g = lane >> 2, c = lane & 3;
    const uint4* __restrict__ B = g_wb + widx * (NKB * 16 * 32);

    float d[4][2][4];
#pragma unroll
    for (int mt = 0; mt < 4; mt++)
#pragma unroll
        for (int nt = 0; nt < 2; nt++)
#pragma unroll
            for (int i = 0; i < 4; i++) d[mt][nt][i] = 0.f;

    uint4 bc[2], bn[2];
    bc[0] = B[(warp * 2 + 0) * 32 + lane];
    bc[1] = B[(warp * 2 + 1) * 32 + lane];

#pragma unroll
    for (int kb = 0; kb < NKB; kb++) {
        if (kb + 1 < NKB) {
            bn[0] = B[((kb + 1) * 16 + warp * 2 + 0) * 32 + lane];
            bn[1] = B[((kb + 1) * 16 + warp * 2 + 1) * 32 + lane];
        }
        // A fragments: 4 m-tiles, hi+lo planes (pure LDS, conflict-free)
        uint32_t ah[4][4], al[4][4];
#pragma unroll
        for (int mt = 0; mt < 4; mt++) {
            const int base = (mt * 16 + g) * APAD + kb * 8 + c;
            ah[mt][0] = srcH[base];
            ah[mt][1] = srcH[base + 8 * APAD];
            ah[mt][2] = srcH[base + 4];
            ah[mt][3] = srcH[base + 8 * APAD + 4];
            al[mt][0] = srcL[base];
            al[mt][1] = srcL[base + 8 * APAD];
            al[mt][2] = srcL[base + 4];
            al[mt][3] = srcL[base + 8 * APAD + 4];
        }
#pragma unroll
        for (int nt = 0; nt < 2; nt++) {
            const uint32_t bh0 = bc[nt].x, bh1 = bc[nt].y;
            const uint32_t bl0 = bc[nt].z, bl1 = bc[nt].w;
#pragma unroll
            for (int mt = 0; mt < 4; mt++) {
                mma_bf16(d[mt][nt], ah[mt][0], ah[mt][1], ah[mt][2], ah[mt][3], bh0, bh1);
                mma_bf16(d[mt][nt], ah[mt][0], ah[mt][1], ah[mt][2], ah[mt][3], bl0, bl1);
                mma_bf16(d[mt][nt], al[mt][0], al[mt][1], al[mt][2], al[mt][3], bh0, bh1);
            }
        }
        bc[0] = bn[0];
        bc[1] = bn[1];
    }

    // epilogue (C layout same as m16n8k8)
    const int c2 = (lane & 3) * 2;
#pragma unroll
    for (int mt = 0; mt < 4; mt++)
#pragma unroll
        for (int nt = 0; nt < 2; nt++) {
            const int row = mt * 16 + g;
            const int col = warp * 16 + nt * 8 + c2;
            if (TOGLOBAL) {
                const float b0v = bias[col];
                const float b1v = bias[col + 1];
                *reinterpret_cast<float2*>(dstG + (size_t)row * kC + col) =
                    make_float2(d[mt][nt][0] + b0v, d[mt][nt][1] + b1v);
                *reinterpret_cast<float2*>(dstG + (size_t)(row + 8) * kC + col) =
                    make_float2(d[mt][nt][2] + b0v, d[mt][nt][3] + b1v);
            } else {
                *reinterpret_cast<float2*>(dstS + row * SPAD + col) =
                    make_float2(d[mt][nt][0], d[mt][nt][1]);
                *reinterpret_cast<float2*>(dstS + (row + 8) * SPAD + col) =
                    make_float2(d[mt][nt][2], d[mt][nt][3]);
            }
        }
}

// Pre-split + swizzle weights. One thread per (mat, kb, n8, lane) -> one uint4.
__global__ void presplit_kernel(const float* __restrict__ Wq,
                                const float* __restrict__ Wk,
                                const float* __restrict__ Wv,
                                const float* __restrict__ Wp) {
    const float* src[4] = {Wq, Wk, Wv, Wp};
    const int idx  = blockIdx.x * blockDim.x + threadIdx.x;  // 0..16383
    const int lane = idx & 31;
    const int n8   = (idx >> 5) & 15;
    const int kb   = (idx >> 9) & 7;
    const int m    = idx >> 12;
    const int n    = n8 * 8 + (lane >> 2);
    const int c    = lane & 3;
    const int k0   = kb * 16 + 2 * c;
    const float w0 = src[m][n * kC + k0];
    const float w1 = src[m][n * kC + k0 + 1];
    const float w8 = src[m][n * kC + k0 + 8];
    const float w9 = src[m][n * kC + k0 + 9];
    uint4 q;
    uint32_t l01, l89;
    split_pair(w0, w1, q.x, l01);   // bh0 / bl0
    split_pair(w8, w9, q.y, l89);   // bh1 / bl1
    q.z = l01;
    q.w = l89;
    g_wb[idx] = q;
}

__global__ __launch_bounds__(256, 2)
void mha_fused_kernel(const float* __restrict__ x,
                      const float* __restrict__ bp,
                      float* __restrict__ out) {
    extern __shared__ float smem[];
    uint32_t* sxh = reinterpret_cast<uint32_t*>(smem + SM_XH);  // x hi, later o hi
    uint32_t* sxl = reinterpret_cast<uint32_t*>(smem + SM_XL);  // x lo, later o lo
    float* sa = smem + SM_A;   // q, later p
    float* sb = smem + SM_B;   // k, later v

    const int tid  = threadIdx.x;
    const int warp = tid >> 5;
    const int lane = tid & 31;
    const int b0   = blockIdx.x * kG;

    // ---- load x (2 batches), split to packed bf16x2 hi/lo planes ----
    const float4* gx = reinterpret_cast<const float4*>(x + (size_t)b0 * kT * kC);
#pragma unroll
    for (int i = 0; i < 8; i++) {
        const int f = tid + 256 * i;          // 0..2047
        const int row = f >> 5, c4 = f & 31;  // c4: float4 index in row
        const float4 v = gx[f];
        uint32_t h2a, l2a, h2b, l2b;
        split_pair(v.x, v.y, h2a, l2a);
        split_pair(v.z, v.w, h2b, l2b);
        const int o = row * APAD + c4 * 2;
        sxh[o] = h2a; sxh[o + 1] = h2b;
        sxl[o] = l2a; sxl[o + 1] = l2b;
    }
    __syncthreads();

    // ---- Q, K projections ----
    gemm3bf<false>(sxh, sxl, 0, sa, nullptr, nullptr, tid);
    gemm3bf<false>(sxh, sxl, 1, sb, nullptr, nullptr, tid);
    __syncthreads();

    // ---- QK^T + causal softmax: warp = (batch, head) ----
    {
        const int rb = (warp >> 2) * kT;
        const int cb = (warp & 3) * kHD;
        const float NEG_INF = __int_as_float(0xff800000u);
        const float scale = 11.3137084989847604f;  // sqrt(128), applied after mask

        float kreg[32];
#pragma unroll
        for (int i = 0; i < 8; i++) {
            const float4 kv = *reinterpret_cast<const float4*>(sb + (rb + lane) * SPAD + cb + 4 * i);
            kreg[4 * i + 0] = kv.x; kreg[4 * i + 1] = kv.y;
            kreg[4 * i + 2] = kv.z; kreg[4 * i + 3] = kv.w;
        }
#pragma unroll 8
        for (int t = 0; t < kT; t++) {
            const float4* qrow = reinterpret_cast<const float4*>(sa + (rb + t) * SPAD + cb);
            float a0 = 0.f, a1 = 0.f, a2 = 0.f, a3 = 0.f;   // 4 chains
#pragma unroll
            for (int i = 0; i < 8; i += 2) {
                const float4 q4 = qrow[i];
                const float4 q5 = qrow[i + 1];
                a0 = fmaf(q4.x, kreg[4 * i + 0], a0);
                a1 = fmaf(q4.y, kreg[4 * i + 1], a1);
                a2 = fmaf(q4.z, kreg[4 * i + 2], a2);
                a3 = fmaf(q4.w, kreg[4 * i + 3], a3);
                a0 = fmaf(q5.x, kreg[4 * i + 4], a0);
                a1 = fmaf(q5.y, kreg[4 * i + 5], a1);
                a2 = fmaf(q5.z, kreg[4 * i + 6], a2);
                a3 = fmaf(q5.w, kreg[4 * i + 7], a3);
            }
            const float acc = (a0 + a1) + (a2 + a3);
            float logit = (lane <= t) ? acc * scale : NEG_INF;
            float mx = logit;
#pragma unroll
            for (int off = 16; off; off >>= 1)
                mx = fmaxf(mx, __shfl_xor_sync(0xffffffffu, mx, off));
            const float e = __expf(logit - mx);
            float s = e;
#pragma unroll
            for (int off = 16; off; off >>= 1)
                s += __shfl_xor_sync(0xffffffffu, s, off);
            sa[(rb + t) * SPAD + cb + lane] = e * (1.0f / s);  // p overwrites q
        }
    }
    __syncthreads();

    // ---- V projection (overwrites k) ----
    gemm3bf<false>(sxh, sxl, 2, sb, nullptr, nullptr, tid);
    __syncthreads();

    // ---- PV: o = p @ v -> packed bf16x2 hi/lo planes (x dead) ----
    {
        const int rb = (warp >> 2) * kT;
        const int cb = (warp & 3) * kHD;
        float vreg[32];
#pragma unroll
        for (int s = 0; s < 32; s++)
            vreg[s] = sb[(rb + s) * SPAD + cb + lane];
#pragma unroll 8
        for (int t = 0; t < kT; t++) {
            const float4* prow = reinterpret_cast<const float4*>(sa + (rb + t) * SPAD + cb);
            float a0 = 0.f, a1 = 0.f, a2 = 0.f, a3 = 0.f;
#pragma unroll
            for (int i = 0; i < 8; i += 2) {
                const float4 p4 = prow[i];
                const float4 p5 = prow[i + 1];
                a0 = fmaf(p4.x, vreg[4 * i + 0], a0);
                a1 = fmaf(p4.y, vreg[4 * i + 1], a1);
                a2 = fmaf(p4.z, vreg[4 * i + 2], a2);
                a3 = fmaf(p4.w, vreg[4 * i + 3], a3);
                a0 = fmaf(p5.x, vreg[4 * i + 4], a0);
                a1 = fmaf(p5.y, vreg[4 * i + 5], a1);
                a2 = fmaf(p5.z, vreg[4 * i + 6], a2);
                a3 = fmaf(p5.w, vreg[4 * i + 7], a3);
            }
            const float od = (a0 + a1) + (a2 + a3);
            const float on = __shfl_down_sync(0xffffffffu, od, 1);
            if (!(lane & 1)) {
                uint32_t h2, l2;
                split_pair(od, on, h2, l2);
                const int o = (rb + t) * APAD + ((cb + lane) >> 1);
                sxh[o] = h2;   // o hi plane
                sxl[o] = l2;   // o lo plane
            }
        }
    }
    __syncthreads();

    // ---- output projection + bias -> global ----
    gemm3bf<true>(sxh, sxl, 3, nullptr, out + (size_t)b0 * kT * kC, bp, tid);
}

} // namespace

extern "C" void kernel_launch(void* const* d_in, const int* in_sizes, int n_in,
                              void* d_out, int out_size) {
    const float* x  = (const float*)d_in[0];
    const float* Wq = (const float*)d_in[1];
    const float* Wk = (const float*)d_in[2];
    const float* Wv = (const float*)d_in[3];
    const float* Wp = (const float*)d_in[4];
    const float* bp = (const float*)d_in[5];
    float* out = (float*)d_out;

    presplit_kernel<<<64, 256>>>(Wq, Wk, Wv, Wp);

    cudaFuncSetAttribute(mha_fused_kernel,
                         cudaFuncAttributeMaxDynamicSharedMemorySize, SMEM_BYTES);
    mha_fused_kernel<<<16384 / kG, 256, SMEM_BYTES>>>(x, bp, out);
}

// round 11
// speedup vs baseline: 3.0083x; 1.4755x over previous
#include <cuda_runtime.h>
#include <cuda_bf16.h>
#include <cstdint>
#include <cstddef>

// Fused MHA, round 10.
// Projections: unchanged R7 structure (3-term bf16x2 mma.sync, pre-split
// weights in L2, packed bf16x2 hi/lo activation planes).
// NEW: attention (QK^T and PV) on tensor cores too — bf16 3-term mma with
// register-resident softmax; P converted C-frag -> A-frag in registers and
// staged through the warp's own dead q block (rotation-indexed, warp-private).

namespace {

constexpr int kT  = 32;
constexpr int kC  = 128;
constexpr int kHD = 32;
constexpr int kG  = 2;                  // batches per CTA
constexpr int ROWS = kG * kT;           // 64
constexpr int SPAD = 132;               // fp32 tile stride (floats)
constexpr int APAD = 68;                // packed-pair plane stride (b32 units)
constexpr int NKB  = 8;                 // k-slices of width 16

// pre-split weights: [mat][kb][n8 tile][lane] = (bh0,bh1,bl0,bl1)
__device__ uint4 g_wb[4 * NKB * 16 * 32];   // 256 KB

constexpr int SM_XH = 0;
constexpr int SM_XL = SM_XH + ROWS * APAD;
constexpr int SM_A  = SM_XL + ROWS * APAD;   // q, then P spill buffer
constexpr int SM_B  = SM_A + ROWS * SPAD;    // k, then v
constexpr int SMEM_WORDS = SM_B + ROWS * SPAD;
constexpr int SMEM_BYTES = SMEM_WORDS * 4;   // 102400 B -> 2 CTAs/SM

__device__ __forceinline__ uint32_t packbf(float hi_el, float lo_el) {
    uint32_t r;
    asm("cvt.rn.bf16x2.f32 %0, %1, %2;" : "=r"(r) : "f"(hi_el), "f"(lo_el));
    return r;
}

// split fp32 pair (x0 -> low half, x1 -> high half) into bf16 hi + residual lo
__device__ __forceinline__ void split_pair(float x0, float x1, uint32_t& h2, uint32_t& l2) {
    h2 = packbf(x1, x0);
    const float h0 = __bfloat162float(__ushort_as_bfloat16((unsigned short)(h2 & 0xffffu)));
    const float h1 = __bfloat162float(__ushort_as_bfloat16((unsigned short)(h2 >> 16)));
    l2 = packbf(x1 - h1, x0 - h0);
}

__device__ __forceinline__ void mma_bf16(float d[4],
                                         uint32_t a0, uint32_t a1, uint32_t a2, uint32_t a3,
                                         uint32_t b0, uint32_t b1) {
    asm("mma.sync.aligned.m16n8k16.row.col.f32.bf16.bf16.f32 "
        "{%0,%1,%2,%3}, {%4,%5,%6,%7}, {%8,%9}, {%0,%1,%2,%3};"
        : "+f"(d[0]), "+f"(d[1]), "+f"(d[2]), "+f"(d[3])
        : "r"(a0), "r"(a1), "r"(a2), "r"(a3), "r"(b0), "r"(b1));
}

// C[64,128] = A[64,128] @ W^T, 3-term bf16x2, barrier-free. (unchanged R7)
template<bool TOGLOBAL>
__device__ __forceinline__ void gemm3bf(const uint32_t* __restrict__ srcH,
                                        const uint32_t* __restrict__ srcL,
                                        int widx,
                                        float* __restrict__ dstS,
                                        float* __restrict__ dstG,
                                        const float* __restrict__ bias,
                                        int tid) {
    const int warp = tid >> 5, lane = tid & 31;
    const int g = lane >> 2, c = lane & 3;
    const uint4* __restrict__ B = g_wb + widx * (NKB * 16 * 32);

    float d[4][2][4];
#pragma unroll
    for (int mt = 0; mt < 4; mt++)
#pragma unroll
        for (int nt = 0; nt < 2; nt++)
#pragma unroll
            for (int i = 0; i < 4; i++) d[mt][nt][i] = 0.f;

    uint4 bc[2], bn[2];
    bc[0] = B[(warp * 2 + 0) * 32 + lane];
    bc[1] = B[(warp * 2 + 1) * 32 + lane];

#pragma unroll
    for (int kb = 0; kb < NKB; kb++) {
        if (kb + 1 < NKB) {
            bn[0] = B[((kb + 1) * 16 + warp * 2 + 0) * 32 + lane];
            bn[1] = B[((kb + 1) * 16 + warp * 2 + 1) * 32 + lane];
        }
        uint32_t ah[4][4], al[4][4];
#pragma unroll
        for (int mt = 0; mt < 4; mt++) {
            const int base = (mt * 16 + g) * APAD + kb * 8 + c;
            ah[mt][0] = srcH[base];
            ah[mt][1] = srcH[base + 8 * APAD];
            ah[mt][2] = srcH[base + 4];
            ah[mt][3] = srcH[base + 8 * APAD + 4];
            al[mt][0] = srcL[base];
            al[mt][1] = srcL[base + 8 * APAD];
            al[mt][2] = srcL[base + 4];
            al[mt][3] = srcL[base + 8 * APAD + 4];
        }
#pragma unroll
        for (int nt = 0; nt < 2; nt++) {
            const uint32_t bh0 = bc[nt].x, bh1 = bc[nt].y;
            const uint32_t bl0 = bc[nt].z, bl1 = bc[nt].w;
#pragma unroll
            for (int mt = 0; mt < 4; mt++) {
                mma_bf16(d[mt][nt], ah[mt][0], ah[mt][1], ah[mt][2], ah[mt][3], bh0, bh1);
                mma_bf16(d[mt][nt], ah[mt][0], ah[mt][1], ah[mt][2], ah[mt][3], bl0, bl1);
                mma_bf16(d[mt][nt], al[mt][0], al[mt][1], al[mt][2], al[mt][3], bh0, bh1);
            }
        }
        bc[0] = bn[0];
        bc[1] = bn[1];
    }

    const int c2 = (lane & 3) * 2;
#pragma unroll
    for (int mt = 0; mt < 4; mt++)
#pragma unroll
        for (int nt = 0; nt < 2; nt++) {
            const int row = mt * 16 + g;
            const int col = warp * 16 + nt * 8 + c2;
            if (TOGLOBAL) {
                const float b0v = bias[col];
                const float b1v = bias[col + 1];
                *reinterpret_cast<float2*>(dstG + (size_t)row * kC + col) =
                    make_float2(d[mt][nt][0] + b0v, d[mt][nt][1] + b1v);
                *reinterpret_cast<float2*>(dstG + (size_t)(row + 8) * kC + col) =
                    make_float2(d[mt][nt][2] + b0v, d[mt][nt][3] + b1v);
            } else {
                *reinterpret_cast<float2*>(dstS + row * SPAD + col) =
                    make_float2(d[mt][nt][0], d[mt][nt][1]);
                *reinterpret_cast<float2*>(dstS + (row + 8) * SPAD + col) =
                    make_float2(d[mt][nt][2], d[mt][nt][3]);
            }
        }
}

__global__ void presplit_kernel(const float* __restrict__ Wq,
                                const float* __restrict__ Wk,
                                const float* __restrict__ Wv,
                                const float* __restrict__ Wp) {
    const float* src[4] = {Wq, Wk, Wv, Wp};
    const int idx  = blockIdx.x * blockDim.x + threadIdx.x;  // 0..16383
    const int lane = idx & 31;
    const int n8   = (idx >> 5) & 15;
    const int kb   = (idx >> 9) & 7;
    const int m    = idx >> 12;
    const int n    = n8 * 8 + (lane >> 2);
    const int c    = lane & 3;
    const int k0   = kb * 16 + 2 * c;
    const float w0 = src[m][n * kC + k0];
    const float w1 = src[m][n * kC + k0 + 1];
    const float w8 = src[m][n * kC + k0 + 8];
    const float w9 = src[m][n * kC + k0 + 9];
    uint4 q;
    uint32_t l01, l89;
    split_pair(w0, w1, q.x, l01);
    split_pair(w8, w9, q.y, l89);
    q.z = l01;
    q.w = l89;
    g_wb[idx] = q;
}

__global__ __launch_bounds__(256, 2)
void mha_fused_kernel(const float* __restrict__ x,
                      const float* __restrict__ bp,
                      float* __restrict__ out) {
    extern __shared__ float smem[];
    uint32_t* sxh = reinterpret_cast<uint32_t*>(smem + SM_XH);  // x hi, later o hi
    uint32_t* sxl = reinterpret_cast<uint32_t*>(smem + SM_XL);  // x lo, later o lo
    float* sa = smem + SM_A;   // q fp32, later per-warp P spill
    float* sb = smem + SM_B;   // k fp32, later v fp32

    const int tid  = threadIdx.x;
    const int warp = tid >> 5;
    const int lane = tid & 31;
    const int b0   = blockIdx.x * kG;

    const int g = lane >> 2, c = lane & 3;
    const int rb = (warp >> 2) * kT;       // batch row block for attention
    const int cb = (warp & 3) * kHD;       // head col block

    // ---- load x (2 batches), split to packed bf16x2 hi/lo planes ----
    const float4* gx = reinterpret_cast<const float4*>(x + (size_t)b0 * kT * kC);
#pragma unroll
    for (int i = 0; i < 8; i++) {
        const int f = tid + 256 * i;
        const int row = f >> 5, c4 = f & 31;
        const float4 v = gx[f];
        uint32_t h2a, l2a, h2b, l2b;
        split_pair(v.x, v.y, h2a, l2a);
        split_pair(v.z, v.w, h2b, l2b);
        const int o = row * APAD + c4 * 2;
        sxh[o] = h2a; sxh[o + 1] = h2b;
        sxl[o] = l2a; sxl[o + 1] = l2b;
    }
    __syncthreads();

    // ---- Q, K projections ----
    gemm3bf<false>(sxh, sxl, 0, sa, nullptr, nullptr, tid);
    gemm3bf<false>(sxh, sxl, 1, sb, nullptr, nullptr, tid);
    __syncthreads();

    // ---- QK^T on tensor cores + register softmax: warp = (batch, head) ----
    float* const pbuf = sa + (rb + lane) * SPAD + cb;   // warp-private P spill (dead q block)
    {
        const float NEG_INF = __int_as_float(0xff800000u);
        const float scale = 11.3137084989847604f;  // sqrt(128), applied after mask

        // A frags from q (fp32 -> hi/lo on the fly)
        uint32_t qh[2][2][4], ql[2][2][4];
#pragma unroll
        for (int mt = 0; mt < 2; mt++)
#pragma unroll
            for (int kb = 0; kb < 2; kb++) {
                const int row = rb + mt * 16 + g;
                const int col = cb + kb * 16 + 2 * c;
                split_pair(sa[row * SPAD + col],           sa[row * SPAD + col + 1],           qh[mt][kb][0], ql[mt][kb][0]);
                split_pair(sa[(row + 8) * SPAD + col],     sa[(row + 8) * SPAD + col + 1],     qh[mt][kb][1], ql[mt][kb][1]);
                split_pair(sa[row * SPAD + col + 8],       sa[row * SPAD + col + 9],           qh[mt][kb][2], ql[mt][kb][2]);
                split_pair(sa[(row + 8) * SPAD + col + 8], sa[(row + 8) * SPAD + col + 9],     qh[mt][kb][3], ql[mt][kb][3]);
            }
        // B frags from k
        uint32_t kh[4][2][2], kl[4][2][2];
#pragma unroll
        for (int nt = 0; nt < 4; nt++)
#pragma unroll
            for (int kb = 0; kb < 2; kb++) {
                const int srow = rb + nt * 8 + g;
                const int col  = cb + kb * 16 + 2 * c;
                split_pair(sb[srow * SPAD + col],     sb[srow * SPAD + col + 1], kh[nt][kb][0], kl[nt][kb][0]);
                split_pair(sb[srow * SPAD + col + 8], sb[srow * SPAD + col + 9], kh[nt][kb][1], kl[nt][kb][1]);
            }

        float dqk[2][4][4];
#pragma unroll
        for (int mt = 0; mt < 2; mt++)
#pragma unroll
            for (int nt = 0; nt < 4; nt++)
#pragma unroll
                for (int i = 0; i < 4; i++) dqk[mt][nt][i] = 0.f;

#pragma unroll
        for (int kb = 0; kb < 2; kb++)
#pragma unroll
            for (int nt = 0; nt < 4; nt++)
#pragma unroll
                for (int mt = 0; mt < 2; mt++) {
                    mma_bf16(dqk[mt][nt], qh[mt][kb][0], qh[mt][kb][1], qh[mt][kb][2], qh[mt][kb][3],
                             kh[nt][kb][0], kh[nt][kb][1]);
                    mma_bf16(dqk[mt][nt], qh[mt][kb][0], qh[mt][kb][1], qh[mt][kb][2], qh[mt][kb][3],
                             kl[nt][kb][0], kl[nt][kb][1]);
                    mma_bf16(dqk[mt][nt], ql[mt][kb][0], ql[mt][kb][1], ql[mt][kb][2], ql[mt][kb][3],
                             kh[nt][kb][0], kh[nt][kb][1]);
                }

        // mask (-inf first), scale, softmax — all in fragments
#pragma unroll
        for (int mt = 0; mt < 2; mt++) {
            const int t0 = mt * 16 + g, t1 = t0 + 8;
            float m0 = NEG_INF, m1 = NEG_INF;
#pragma unroll
            for (int nt = 0; nt < 4; nt++) {
                const int s0 = nt * 8 + 2 * c;
                float* dd = dqk[mt][nt];
                dd[0] = (s0     <= t0) ? dd[0] * scale : NEG_INF;
                dd[1] = (s0 + 1 <= t0) ? dd[1] * scale : NEG_INF;
                dd[2] = (s0     <= t1) ? dd[2] * scale : NEG_INF;
                dd[3] = (s0 + 1 <= t1) ? dd[3] * scale : NEG_INF;
                m0 = fmaxf(m0, fmaxf(dd[0], dd[1]));
                m1 = fmaxf(m1, fmaxf(dd[2], dd[3]));
            }
            m0 = fmaxf(m0, __shfl_xor_sync(0xffffffffu, m0, 1));
            m0 = fmaxf(m0, __shfl_xor_sync(0xffffffffu, m0, 2));
            m1 = fmaxf(m1, __shfl_xor_sync(0xffffffffu, m1, 1));
            m1 = fmaxf(m1, __shfl_xor_sync(0xffffffffu, m1, 2));
            float sum0 = 0.f, sum1 = 0.f;
#pragma unroll
            for (int nt = 0; nt < 4; nt++) {
                float* dd = dqk[mt][nt];
                dd[0] = __expf(dd[0] - m0);
                dd[1] = __expf(dd[1] - m0);
                dd[2] = __expf(dd[2] - m1);
                dd[3] = __expf(dd[3] - m1);
                sum0 += dd[0] + dd[1];
                sum1 += dd[2] + dd[3];
            }
            sum0 += __shfl_xor_sync(0xffffffffu, sum0, 1);
            sum0 += __shfl_xor_sync(0xffffffffu, sum0, 2);
            sum1 += __shfl_xor_sync(0xffffffffu, sum1, 1);
            sum1 += __shfl_xor_sync(0xffffffffu, sum1, 2);
            const float r0 = 1.0f / sum0, r1 = 1.0f / sum1;
#pragma unroll
            for (int nt = 0; nt < 4; nt++) {
                float* dd = dqk[mt][nt];
                dd[0] *= r0; dd[1] *= r0; dd[2] *= r1; dd[3] *= r1;
            }
        }

        // C-frag -> PV A-frag (register-local), spill hi/lo to warp-private buffer.
        // slot s stored at pbuf[(s + lane) & 31] (rotation: conflict-free).
#pragma unroll
        for (int mt = 0; mt < 2; mt++)
#pragma unroll
            for (int kb = 0; kb < 2; kb++) {
                const int base = (mt * 2 + kb) * 4;
                uint32_t h, l;
                split_pair(dqk[mt][2 * kb][0],     dqk[mt][2 * kb][1],     h, l);
                pbuf[(base + 0 + lane) & 31]  = __uint_as_float(h);
                pbuf[(base + 16 + lane) & 31] = __uint_as_float(l);
                split_pair(dqk[mt][2 * kb][2],     dqk[mt][2 * kb][3],     h, l);
                pbuf[(base + 1 + lane) & 31]  = __uint_as_float(h);
                pbuf[(base + 17 + lane) & 31] = __uint_as_float(l);
                split_pair(dqk[mt][2 * kb + 1][0], dqk[mt][2 * kb + 1][1], h, l);
                pbuf[(base + 2 + lane) & 31]  = __uint_as_float(h);
                pbuf[(base + 18 + lane) & 31] = __uint_as_float(l);
                split_pair(dqk[mt][2 * kb + 1][2], dqk[mt][2 * kb + 1][3], h, l);
                pbuf[(base + 3 + lane) & 31]  = __uint_as_float(h);
                pbuf[(base + 19 + lane) & 31] = __uint_as_float(l);
            }
    }
    __syncthreads();

    // ---- V projection (overwrites k) ----
    gemm3bf<false>(sxh, sxl, 2, sb, nullptr, nullptr, tid);
    __syncthreads();

    // ---- PV on tensor cores: o = P @ V -> bf16x2 hi/lo planes (x dead) ----
    {
        // reload P frags
        uint32_t ph[2][2][4], pl[2][2][4];
#pragma unroll
        for (int mt = 0; mt < 2; mt++)
#pragma unroll
            for (int kb = 0; kb < 2; kb++)
#pragma unroll
                for (int j = 0; j < 4; j++) {
                    const int s = (mt * 2 + kb) * 4 + j;
                    ph[mt][kb][j] = __float_as_uint(pbuf[(s + lane) & 31]);
                    pl[mt][kb][j] = __float_as_uint(pbuf[(s + 16 + lane) & 31]);
                }
        // V B-frags (fp32 -> hi/lo on the fly); k-dim = s (pairs along rows)
        uint32_t vh[4][2][2], vl[4][2][2];
#pragma unroll
        for (int ntd = 0; ntd < 4; ntd++)
#pragma unroll
            for (int kb = 0; kb < 2; kb++) {
                const int dcol = cb + ntd * 8 + g;
                const int s0   = rb + kb * 16 + 2 * c;
                split_pair(sb[s0 * SPAD + dcol],       sb[(s0 + 1) * SPAD + dcol], vh[ntd][kb][0], vl[ntd][kb][0]);
                split_pair(sb[(s0 + 8) * SPAD + dcol], sb[(s0 + 9) * SPAD + dcol], vh[ntd][kb][1], vl[ntd][kb][1]);
            }

        float dov[2][4][4];
#pragma unroll
        for (int mt = 0; mt < 2; mt++)
#pragma unroll
            for (int nt = 0; nt < 4; nt++)
#pragma unroll
                for (int i = 0; i < 4; i++) dov[mt][nt][i] = 0.f;

#pragma unroll
        for (int kb = 0; kb < 2; kb++)
#pragma unroll
            for (int ntd = 0; ntd < 4; ntd++)
#pragma unroll
                for (int mt = 0; mt < 2; mt++) {
                    mma_bf16(dov[mt][ntd], ph[mt][kb][0], ph[mt][kb][1], ph[mt][kb][2], ph[mt][kb][3],
                             vh[ntd][kb][0], vh[ntd][kb][1]);
                    mma_bf16(dov[mt][ntd], ph[mt][kb][0], ph[mt][kb][1], ph[mt][kb][2], ph[mt][kb][3],
                             vl[ntd][kb][0], vl[ntd][kb][1]);
                    mma_bf16(dov[mt][ntd], pl[mt][kb][0], pl[mt][kb][1], pl[mt][kb][2], pl[mt][kb][3],
                             vh[ntd][kb][0], vh[ntd][kb][1]);
                }

        // epilogue: pack o pairs straight into the out-proj A planes
#pragma unroll
        for (int mt = 0; mt < 2; mt++)
#pragma unroll
            for (int ntd = 0; ntd < 4; ntd++) {
                const int row  = rb + mt * 16 + g;
                const int wcol = (cb >> 1) + ntd * 4 + c;
                uint32_t h, l;
                split_pair(dov[mt][ntd][0], dov[mt][ntd][1], h, l);
                sxh[row * APAD + wcol] = h;
                sxl[row * APAD + wcol] = l;
                split_pair(dov[mt][ntd][2], dov[mt][ntd][3], h, l);
                sxh[(row + 8) * APAD + wcol] = h;
                sxl[(row + 8) * APAD + wcol] = l;
            }
    }
    __syncthreads();

    // ---- output projection + bias -> global ----
    gemm3bf<true>(sxh, sxl, 3, nullptr, out + (size_t)b0 * kT * kC, bp, tid);
}

} // namespace

extern "C" void kernel_launch(void* const* d_in, const int* in_sizes, int n_in,
                              void* d_out, int out_size) {
    const float* x  = (const float*)d_in[0];
    const float* Wq = (const float*)d_in[1];
    const float* Wk = (const float*)d_in[2];
    const float* Wv = (const float*)d_in[3];
    const float* Wp = (const float*)d_in[4];
    const float* bp = (const float*)d_in[5];
    float* out = (float*)d_out;

    presplit_kernel<<<64, 256>>>(Wq, Wk, Wv, Wp);

    cudaFuncSetAttribute(mha_fused_kernel,
                         cudaFuncAttributeMaxDynamicSharedMemorySize, SMEM_BYTES);
    mha_fused_kernel<<<16384 / kG, 256, SMEM_BYTES>>>(x, bp, out);
}

// round 17
// speedup vs baseline: 3.8906x; 1.2933x over previous
#include <cuda_runtime.h>
#include <cuda_bf16.h>
#include <cstdint>
#include <cstddef>

// Fused MHA, round 16. Base = round-10 passing kernel (763 us).
// (1) L2 policy split: weights via 256-bit ld.global.nc.L2::evict_last.v8.b32
//     (layout re-swizzled so a lane's two n8-frags are one 32B line);
//     x via ld.global.cs, out via st.global.cs.
// (2) Projection warp grid 2m x 4n (A-LDS redundancy 8x -> 4x).
// Attention path unchanged from the 763us kernel.

namespace {

constexpr int kT  = 32;
constexpr int kC  = 128;
constexpr int kHD = 32;
constexpr int kG  = 2;                  // batches per CTA
constexpr int ROWS = kG * kT;           // 64
constexpr int SPAD = 132;               // fp32 tile stride (floats)
constexpr int APAD = 68;                // packed-pair plane stride (b32 units)
constexpr int NKB  = 8;                 // k-slices of width 16

// pre-split weights, 32B-granular layout:
// uint4 index = ((mat*8 + kb)*8 + grp)*64 + lane*2 + par,
// where grp = n8>>1, par = n8&1. One 32B line = frags for n8={2*grp, 2*grp+1}.
__device__ __align__(256) uint4 g_wb[4 * NKB * 16 * 32];   // 256 KB

constexpr int SM_XH = 0;
constexpr int SM_XL = SM_XH + ROWS * APAD;
constexpr int SM_A  = SM_XL + ROWS * APAD;   // q, then P spill buffer
constexpr int SM_B  = SM_A + ROWS * SPAD;    // k, then v
constexpr int SMEM_WORDS = SM_B + ROWS * SPAD;
constexpr int SMEM_BYTES = SMEM_WORDS * 4;   // 102400 B -> 2 CTAs/SM

// ---- cache-policy load/store helpers ----
// weights: 256-bit keep-in-L2 load (the only form ptxas accepts evict_last on)
__device__ __forceinline__ void ldg_evl8(const uint4* p, uint4& a, uint4& b) {
    asm volatile("ld.global.nc.L2::evict_last.v8.b32 {%0,%1,%2,%3,%4,%5,%6,%7}, [%8];"
                 : "=r"(a.x), "=r"(a.y), "=r"(a.z), "=r"(a.w),
                   "=r"(b.x), "=r"(b.y), "=r"(b.z), "=r"(b.w)
                 : "l"(p));
}
__device__ __forceinline__ float4 ldg_cs(const float4* p) {  // x: streaming
    float4 v;
    asm volatile("ld.global.cs.v4.f32 {%0,%1,%2,%3}, [%4];"
                 : "=f"(v.x), "=f"(v.y), "=f"(v.z), "=f"(v.w) : "l"(p));
    return v;
}
__device__ __forceinline__ void stg_cs2(float* p, float a, float b) {  // out: streaming
    asm volatile("st.global.cs.v2.f32 [%0], {%1,%2};" :: "l"(p), "f"(a), "f"(b) : "memory");
}

__device__ __forceinline__ uint32_t packbf(float hi_el, float lo_el) {
    uint32_t r;
    asm("cvt.rn.bf16x2.f32 %0, %1, %2;" : "=r"(r) : "f"(hi_el), "f"(lo_el));
    return r;
}

// split fp32 pair (x0 -> low half, x1 -> high half) into bf16 hi + residual lo
__device__ __forceinline__ void split_pair(float x0, float x1, uint32_t& h2, uint32_t& l2) {
    h2 = packbf(x1, x0);
    const float h0 = __bfloat162float(__ushort_as_bfloat16((unsigned short)(h2 & 0xffffu)));
    const float h1 = __bfloat162float(__ushort_as_bfloat16((unsigned short)(h2 >> 16)));
    l2 = packbf(x1 - h1, x0 - h0);
}

__device__ __forceinline__ void mma_bf16(float d[4],
                                         uint32_t a0, uint32_t a1, uint32_t a2, uint32_t a3,
                                         uint32_t b0, uint32_t b1) {
    asm("mma.sync.aligned.m16n8k16.row.col.f32.bf16.bf16.f32 "
        "{%0,%1,%2,%3}, {%4,%5,%6,%7}, {%8,%9}, {%0,%1,%2,%3};"
        : "+f"(d[0]), "+f"(d[1]), "+f"(d[2]), "+f"(d[3])
        : "r"(a0), "r"(a1), "r"(a2), "r"(a3), "r"(b0), "r"(b1));
}

// C[64,128] = A[64,128] @ W^T, 3-term bf16x2, barrier-free.
// Warp grid 2m x 4n: mi = warp>>2 in {0,1}, nj = warp&3.
// Warp covers m-tiles {2mi, 2mi+1} and n-cols [32nj, 32nj+32) (4 n8 tiles).
template<bool TOGLOBAL>
__device__ __forceinline__ void gemm3bf(const uint32_t* __restrict__ srcH,
                                        const uint32_t* __restrict__ srcL,
                                        int widx,
                                        float* __restrict__ dstS,
                                        float* __restrict__ dstG,
                                        const float* __restrict__ bias,
                                        int tid) {
    const int warp = tid >> 5, lane = tid & 31;
    const int mi = warp >> 2, nj = warp & 3;
    const int g = lane >> 2, c = lane & 3;
    const uint4* __restrict__ B = g_wb + widx * (NKB * 16 * 32);

    float d[2][4][4];
#pragma unroll
    for (int mt = 0; mt < 2; mt++)
#pragma unroll
        for (int nt = 0; nt < 4; nt++)
#pragma unroll
            for (int i = 0; i < 4; i++) d[mt][nt][i] = 0.f;

    uint4 bc[4], bn[4];
    // grp index for (kb, nt-pair p): kb*8 + nj*2 + p; uint4 addr = grp*64 + lane*2
#pragma unroll
    for (int p = 0; p < 2; p++)
        ldg_evl8(&B[(nj * 2 + p) * 64 + lane * 2], bc[2 * p], bc[2 * p + 1]);

#pragma unroll
    for (int kb = 0; kb < NKB; kb++) {
        if (kb + 1 < NKB) {
#pragma unroll
            for (int p = 0; p < 2; p++)
                ldg_evl8(&B[((kb + 1) * 8 + nj * 2 + p) * 64 + lane * 2],
                         bn[2 * p], bn[2 * p + 1]);
        }
        uint32_t ah[2][4], al[2][4];
#pragma unroll
        for (int mt = 0; mt < 2; mt++) {
            const int base = ((mi * 2 + mt) * 16 + g) * APAD + kb * 8 + c;
            ah[mt][0] = srcH[base];
            ah[mt][1] = srcH[base + 8 * APAD];
            ah[mt][2] = srcH[base + 4];
            ah[mt][3] = srcH[base + 8 * APAD + 4];
            al[mt][0] = srcL[base];
            al[mt][1] = srcL[base + 8 * APAD];
            al[mt][2] = srcL[base + 4];
            al[mt][3] = srcL[base + 8 * APAD + 4];
        }
#pragma unroll
        for (int nt = 0; nt < 4; nt++) {
            const uint32_t bh0 = bc[nt].x, bh1 = bc[nt].y;
            const uint32_t bl0 = bc[nt].z, bl1 = bc[nt].w;
#pragma unroll
            for (int mt = 0; mt < 2; mt++) {
                mma_bf16(d[mt][nt], ah[mt][0], ah[mt][1], ah[mt][2], ah[mt][3], bh0, bh1);
                mma_bf16(d[mt][nt], ah[mt][0], ah[mt][1], ah[mt][2], ah[mt][3], bl0, bl1);
                mma_bf16(d[mt][nt], al[mt][0], al[mt][1], al[mt][2], al[mt][3], bh0, bh1);
            }
        }
#pragma unroll
        for (int nt = 0; nt < 4; nt++) bc[nt] = bn[nt];
    }

    const int c2 = (lane & 3) * 2;
#pragma unroll
    for (int mt = 0; mt < 2; mt++)
#pragma unroll
        for (int nt = 0; nt < 4; nt++) {
            const int row = (mi * 2 + mt) * 16 + g;
            const int col = nj * 32 + nt * 8 + c2;
            if (TOGLOBAL) {
                const float b0v = bias[col];
                const float b1v = bias[col + 1];
                stg_cs2(dstG + (size_t)row * kC + col,       d[mt][nt][0] + b0v, d[mt][nt][1] + b1v);
                stg_cs2(dstG + (size_t)(row + 8) * kC + col, d[mt][nt][2] + b0v, d[mt][nt][3] + b1v);
            } else {
                *reinterpret_cast<float2*>(dstS + row * SPAD + col) =
                    make_float2(d[mt][nt][0], d[mt][nt][1]);
                *reinterpret_cast<float2*>(dstS + (row + 8) * SPAD + col) =
                    make_float2(d[mt][nt][2], d[mt][nt][3]);
            }
        }
}

__global__ void presplit_kernel(const float* __restrict__ Wq,
                                const float* __restrict__ Wk,
                                const float* __restrict__ Wv,
                                const float* __restrict__ Wp) {
    const float* src[4] = {Wq, Wk, Wv, Wp};
    const int idx  = blockIdx.x * blockDim.x + threadIdx.x;  // 0..16383
    const int lane = idx & 31;
    const int n8   = (idx >> 5) & 15;
    const int kb   = (idx >> 9) & 7;
    const int m    = idx >> 12;
    const int n    = n8 * 8 + (lane >> 2);
    const int c    = lane & 3;
    const int k0   = kb * 16 + 2 * c;
    const float w0 = src[m][n * kC + k0];
    const float w1 = src[m][n * kC + k0 + 1];
    const float w8 = src[m][n * kC + k0 + 8];
    const float w9 = src[m][n * kC + k0 + 9];
    uint4 q;
    uint32_t l01, l89;
    split_pair(w0, w1, q.x, l01);
    split_pair(w8, w9, q.y, l89);
    q.z = l01;
    q.w = l89;
    // 32B-granular layout: grp = n8>>1, par = n8&1
    const int dst = ((m * NKB + kb) * 8 + (n8 >> 1)) * 64 + lane * 2 + (n8 & 1);
    g_wb[dst] = q;
}

__global__ __launch_bounds__(256, 2)
void mha_fused_kernel(const float* __restrict__ x,
                      const float* __restrict__ bp,
                      float* __restrict__ out) {
    extern __shared__ float smem[];
    uint32_t* sxh = reinterpret_cast<uint32_t*>(smem + SM_XH);  // x hi, later o hi
    uint32_t* sxl = reinterpret_cast<uint32_t*>(smem + SM_XL);  // x lo, later o lo
    float* sa = smem + SM_A;   // q fp32, later per-warp P spill
    float* sb = smem + SM_B;   // k fp32, later v fp32

    const int tid  = threadIdx.x;
    const int warp = tid >> 5;
    const int lane = tid & 31;
    const int b0   = blockIdx.x * kG;

    const int g = lane >> 2, c = lane & 3;
    const int rb = (warp >> 2) * kT;       // batch row block for attention
    const int cb = (warp & 3) * kHD;       // head col block

    // ---- load x (2 batches, streaming), split to packed bf16x2 hi/lo planes ----
    const float4* gx = reinterpret_cast<const float4*>(x + (size_t)b0 * kT * kC);
#pragma unroll
    for (int i = 0; i < 8; i++) {
        const int f = tid + 256 * i;
        const int row = f >> 5, c4 = f & 31;
        const float4 v = ldg_cs(gx + f);
        uint32_t h2a, l2a, h2b, l2b;
        split_pair(v.x, v.y, h2a, l2a);
        split_pair(v.z, v.w, h2b, l2b);
        const int o = row * APAD + c4 * 2;
        sxh[o] = h2a; sxh[o + 1] = h2b;
        sxl[o] = l2a; sxl[o + 1] = l2b;
    }
    __syncthreads();

    // ---- Q, K projections ----
    gemm3bf<false>(sxh, sxl, 0, sa, nullptr, nullptr, tid);
    gemm3bf<false>(sxh, sxl, 1, sb, nullptr, nullptr, tid);
    __syncthreads();

    // ---- QK^T on tensor cores + register softmax: warp = (batch, head) ----
    float* const pbuf = sa + (rb + lane) * SPAD + cb;   // warp-private P spill (dead q block)
    {
        const float NEG_INF = __int_as_float(0xff800000u);
        const float scale = 11.3137084989847604f;  // sqrt(128), applied after mask

        // A frags from q (fp32 -> hi/lo on the fly)
        uint32_t qh[2][2][4], ql[2][2][4];
#pragma unroll
        for (int mt = 0; mt < 2; mt++)
#pragma unroll
            for (int kb = 0; kb < 2; kb++) {
                const int row = rb + mt * 16 + g;
                const int col = cb + kb * 16 + 2 * c;
                split_pair(sa[row * SPAD + col],           sa[row * SPAD + col + 1],           qh[mt][kb][0], ql[mt][kb][0]);
                split_pair(sa[(row + 8) * SPAD + col],     sa[(row + 8) * SPAD + col + 1],     qh[mt][kb][1], ql[mt][kb][1]);
                split_pair(sa[row * SPAD + col + 8],       sa[row * SPAD + col + 9],           qh[mt][kb][2], ql[mt][kb][2]);
                split_pair(sa[(row + 8) * SPAD + col + 8], sa[(row + 8) * SPAD + col + 9],     qh[mt][kb][3], ql[mt][kb][3]);
            }
        // B frags from k
        uint32_t kh[4][2][2], kl[4][2][2];
#pragma unroll
        for (int nt = 0; nt < 4; nt++)
#pragma unroll
            for (int kb = 0; kb < 2; kb++) {
                const int srow = rb + nt * 8 + g;
                const int col  = cb + kb * 16 + 2 * c;
                split_pair(sb[srow * SPAD + col],     sb[srow * SPAD + col + 1], kh[nt][kb][0], kl[nt][kb][0]);
                split_pair(sb[srow * SPAD + col + 8], sb[srow * SPAD + col + 9], kh[nt][kb][1], kl[nt][kb][1]);
            }

        float dqk[2][4][4];
#pragma unroll
        for (int mt = 0; mt < 2; mt++)
#pragma unroll
            for (int nt = 0; nt < 4; nt++)
#pragma unroll
                for (int i = 0; i < 4; i++) dqk[mt][nt][i] = 0.f;

#pragma unroll
        for (int kb = 0; kb < 2; kb++)
#pragma unroll
            for (int nt = 0; nt < 4; nt++)
#pragma unroll
                for (int mt = 0; mt < 2; mt++) {
                    mma_bf16(dqk[mt][nt], qh[mt][kb][0], qh[mt][kb][1], qh[mt][kb][2], qh[mt][kb][3],
                             kh[nt][kb][0], kh[nt][kb][1]);
                    mma_bf16(dqk[mt][nt], qh[mt][kb][0], qh[mt][kb][1], qh[mt][kb][2], qh[mt][kb][3],
                             kl[nt][kb][0], kl[nt][kb][1]);
                    mma_bf16(dqk[mt][nt], ql[mt][kb][0], ql[mt][kb][1], ql[mt][kb][2], ql[mt][kb][3],
                             kh[nt][kb][0], kh[nt][kb][1]);
                }

        // mask (-inf first), scale, softmax — all in fragments
#pragma unroll
        for (int mt = 0; mt < 2; mt++) {
            const int t0 = mt * 16 + g, t1 = t0 + 8;
            float m0 = NEG_INF, m1 = NEG_INF;
#pragma unroll
            for (int nt = 0; nt < 4; nt++) {
                const int s0 = nt * 8 + 2 * c;
                float* dd = dqk[mt][nt];
                dd[0] = (s0     <= t0) ? dd[0] * scale : NEG_INF;
                dd[1] = (s0 + 1 <= t0) ? dd[1] * scale : NEG_INF;
                dd[2] = (s0     <= t1) ? dd[2] * scale : NEG_INF;
                dd[3] = (s0 + 1 <= t1) ? dd[3] * scale : NEG_INF;
                m0 = fmaxf(m0, fmaxf(dd[0], dd[1]));
                m1 = fmaxf(m1, fmaxf(dd[2], dd[3]));
            }
            m0 = fmaxf(m0, __shfl_xor_sync(0xffffffffu, m0, 1));
            m0 = fmaxf(m0, __shfl_xor_sync(0xffffffffu, m0, 2));
            m1 = fmaxf(m1, __shfl_xor_sync(0xffffffffu, m1, 1));
            m1 = fmaxf(m1, __shfl_xor_sync(0xffffffffu, m1, 2));
            float sum0 = 0.f, sum1 = 0.f;
#pragma unroll
            for (int nt = 0; nt < 4; nt++) {
                float* dd = dqk[mt][nt];
                dd[0] = __expf(dd[0] - m0);
                dd[1] = __expf(dd[1] - m0);
                dd[2] = __expf(dd[2] - m1);
                dd[3] = __expf(dd[3] - m1);
                sum0 += dd[0] + dd[1];
                sum1 += dd[2] + dd[3];
            }
            sum0 += __shfl_xor_sync(0xffffffffu, sum0, 1);
            sum0 += __shfl_xor_sync(0xffffffffu, sum0, 2);
            sum1 += __shfl_xor_sync(0xffffffffu, sum1, 1);
            sum1 += __shfl_xor_sync(0xffffffffu, sum1, 2);
            const float r0 = 1.0f / sum0, r1 = 1.0f / sum1;
#pragma unroll
            for (int nt = 0; nt < 4; nt++) {
                float* dd = dqk[mt][nt];
                dd[0] *= r0; dd[1] *= r0; dd[2] *= r1; dd[3] *= r1;
            }
        }

        // C-frag -> PV A-frag (register-local), spill hi/lo to warp-private buffer.
        // slot s stored at pbuf[(s + lane) & 31] (rotation: conflict-free).
#pragma unroll
        for (int mt = 0; mt < 2; mt++)
#pragma unroll
            for (int kb = 0; kb < 2; kb++) {
                const int base = (mt * 2 + kb) * 4;
                uint32_t h, l;
                split_pair(dqk[mt][2 * kb][0],     dqk[mt][2 * kb][1],     h, l);
                pbuf[(base + 0 + lane) & 31]  = __uint_as_float(h);
                pbuf[(base + 16 + lane) & 31] = __uint_as_float(l);
                split_pair(dqk[mt][2 * kb][2],     dqk[mt][2 * kb][3],     h, l);
                pbuf[(base + 1 + lane) & 31]  = __uint_as_float(h);
                pbuf[(base + 17 + lane) & 31] = __uint_as_float(l);
                split_pair(dqk[mt][2 * kb + 1][0], dqk[mt][2 * kb + 1][1], h, l);
                pbuf[(base + 2 + lane) & 31]  = __uint_as_float(h);
                pbuf[(base + 18 + lane) & 31] = __uint_as_float(l);
                split_pair(dqk[mt][2 * kb + 1][2], dqk[mt][2 * kb + 1][3], h, l);
                pbuf[(base + 3 + lane) & 31]  = __uint_as_float(h);
                pbuf[(base + 19 + lane) & 31] = __uint_as_float(l);
            }
    }
    __syncthreads();

    // ---- V projection (overwrites k) ----
    gemm3bf<false>(sxh, sxl, 2, sb, nullptr, nullptr, tid);
    __syncthreads();

    // ---- PV on tensor cores: o = P @ V -> bf16x2 hi/lo planes (x dead) ----
    {
        uint32_t ph[2][2][4], pl[2][2][4];
#pragma unroll
        for (int mt = 0; mt < 2; mt++)
#pragma unroll
            for (int kb = 0; kb < 2; kb++)
#pragma unroll
                for (int j = 0; j < 4; j++) {
                    const int s = (mt * 2 + kb) * 4 + j;
                    ph[mt][kb][j] = __float_as_uint(pbuf[(s + lane) & 31]);
                    pl[mt][kb][j] = __float_as_uint(pbuf[(s + 16 + lane) & 31]);
                }
        uint32_t vh[4][2][2], vl[4][2][2];
#pragma unroll
        for (int ntd = 0; ntd < 4; ntd++)
#pragma unroll
            for (int kb = 0; kb < 2; kb++) {
                const int dcol = cb + ntd * 8 + g;
                const int s0   = rb + kb * 16 + 2 * c;
                split_pair(sb[s0 * SPAD + dcol],       sb[(s0 + 1) * SPAD + dcol], vh[ntd][kb][0], vl[ntd][kb][0]);
                split_pair(sb[(s0 + 8) * SPAD + dcol], sb[(s0 + 9) * SPAD + dcol], vh[ntd][kb][1], vl[ntd][kb][1]);
            }

        float dov[2][4][4];
#pragma unroll
        for (int mt = 0; mt < 2; mt++)
#pragma unroll
            for (int nt = 0; nt < 4; nt++)
#pragma unroll
                for (int i = 0; i < 4; i++) dov[mt][nt][i] = 0.f;

#pragma unroll
        for (int kb = 0; kb < 2; kb++)
#pragma unroll
            for (int ntd = 0; ntd < 4; ntd++)
#pragma unroll
                for (int mt = 0; mt < 2; mt++) {
                    mma_bf16(dov[mt][ntd], ph[mt][kb][0], ph[mt][kb][1], ph[mt][kb][2], ph[mt][kb][3],
                             vh[ntd][kb][0], vh[ntd][kb][1]);
                    mma_bf16(dov[mt][ntd], ph[mt][kb][0], ph[mt][kb][1], ph[mt][kb][2], ph[mt][kb][3],
                             vl[ntd][kb][0], vl[ntd][kb][1]);
                    mma_bf16(dov[mt][ntd], pl[mt][kb][0], pl[mt][kb][1], pl[mt][kb][2], pl[mt][kb][3],
                             vh[ntd][kb][0], vh[ntd][kb][1]);
                }

        // epilogue: pack o pairs straight into the out-proj A planes
#pragma unroll
        for (int mt = 0; mt < 2; mt++)
#pragma unroll
            for (int ntd = 0; ntd < 4; ntd++) {
                const int row  = rb + mt * 16 + g;
                const int wcol = (cb >> 1) + ntd * 4 + c;
                uint32_t h, l;
                split_pair(dov[mt][ntd][0], dov[mt][ntd][1], h, l);
                sxh[row * APAD + wcol] = h;
                sxl[row * APAD + wcol] = l;
                split_pair(dov[mt][ntd][2], dov[mt][ntd][3], h, l);
                sxh[(row + 8) * APAD + wcol] = h;
                sxl[(row + 8) * APAD + wcol] = l;
            }
    }
    __syncthreads();

    // ---- output projection + bias -> global (streaming stores) ----
    gemm3bf<true>(sxh, sxl, 3, nullptr, out + (size_t)b0 * kT * kC, bp, tid);
}

} // namespace

extern "C" void kernel_launch(void* const* d_in, const int* in_sizes, int n_in,
                              void* d_out, int out_size) {
    const float* x  = (const float*)d_in[0];
    const float* Wq = (const float*)d_in[1];
    const float* Wk = (const float*)d_in[2];
    const float* Wv = (const float*)d_in[3];
    const float* Wp = (const float*)d_in[4];
    const float* bp = (const float*)d_in[5];
    float* out = (float*)d_out;

    presplit_kernel<<<64, 256>>>(Wq, Wk, Wv, Wp);

    cudaFuncSetAttribute(mha_fused_kernel,
                         cudaFuncAttributeMaxDynamicSharedMemorySize, SMEM_BYTES);
    mha_fused_kernel<<<16384 / kG, 256, SMEM_BYTES>>>(x, bp, out);
}